// round 4
// baseline (speedup 1.0000x reference)
#include <cuda_runtime.h>
#include <math.h>

#define NTOK   257
#define BATCH  64
#define T_TOK  (BATCH * NTOK)   // 16448
#define DMODEL 1024
#define NHEAD  16
#define HD     64
#define HDIM   4096
#define LN_EPS 1e-5f

// ---------------- scratch (device globals; no allocations allowed) ----------
__device__ float g_xn [(size_t)T_TOK * DMODEL];
__device__ float g_q  [(size_t)T_TOK * DMODEL];
__device__ float g_k  [(size_t)T_TOK * DMODEL];
__device__ float g_v  [(size_t)T_TOK * DMODEL];
__device__ float g_att[(size_t)T_TOK * DMODEL];
__device__ float g_x1 [(size_t)T_TOK * DMODEL];
__device__ float g_h1 [(size_t)T_TOK * HDIM];
__device__ float g_h2 [(size_t)T_TOK * HDIM];

// ---------------- LayerNorm (one row per block, 256 threads) ----------------
template<int W>
__global__ void __launch_bounds__(256) ln_kernel(const float* __restrict__ x,
                                                 const float* __restrict__ g,
                                                 const float* __restrict__ b,
                                                 float* __restrict__ y)
{
    constexpr int V = W / 1024;             // float4s per thread
    __shared__ float red0[8], red1[8];
    __shared__ float stats[2];
    size_t rb = (size_t)blockIdx.x * W;
    const float4* xr = (const float4*)(x + rb);
    float4 vv[V];
    float s = 0.f, s2 = 0.f;
#pragma unroll
    for (int i = 0; i < V; i++) {
        float4 t = xr[threadIdx.x + i * 256];
        vv[i] = t;
        s  += t.x + t.y + t.z + t.w;
        s2 += t.x*t.x + t.y*t.y + t.z*t.z + t.w*t.w;
    }
#pragma unroll
    for (int o = 16; o; o >>= 1) {
        s  += __shfl_xor_sync(0xffffffffu, s,  o);
        s2 += __shfl_xor_sync(0xffffffffu, s2, o);
    }
    if ((threadIdx.x & 31) == 0) { red0[threadIdx.x >> 5] = s; red1[threadIdx.x >> 5] = s2; }
    __syncthreads();
    if (threadIdx.x == 0) {
        float a = 0.f, c = 0.f;
#pragma unroll
        for (int i = 0; i < 8; i++) { a += red0[i]; c += red1[i]; }
        float mu  = a / (float)W;
        float var = c / (float)W - mu * mu;
        stats[0] = mu;
        stats[1] = rsqrtf(var + LN_EPS);
    }
    __syncthreads();
    float mu = stats[0], inv = stats[1];
    float4* yr = (float4*)(y + rb);
    const float4* g4 = (const float4*)g;
    const float4* b4 = (const float4*)b;
#pragma unroll
    for (int i = 0; i < V; i++) {
        int c = threadIdx.x + i * 256;
        float4 gg = g4[c], bb = b4[c], t = vv[i], o;
        o.x = (t.x - mu) * inv * gg.x + bb.x;
        o.y = (t.y - mu) * inv * gg.y + bb.y;
        o.z = (t.z - mu) * inv * gg.z + bb.z;
        o.w = (t.w - mu) * inv * gg.w + bb.w;
        yr[c] = o;
    }
}

// ---------------- fused SiLU(h1)*h2 -> LayerNorm, in place into h1 ----------
__global__ void __launch_bounds__(256) silu_ln_kernel(float* __restrict__ h1,
                                                      const float* __restrict__ h2,
                                                      const float* __restrict__ g,
                                                      const float* __restrict__ b)
{
    constexpr int W = HDIM;
    constexpr int V = W / 1024;  // 4
    __shared__ float red0[8], red1[8];
    __shared__ float stats[2];
    size_t rb = (size_t)blockIdx.x * W;
    const float4* ar = (const float4*)(h1 + rb);
    const float4* cr = (const float4*)(h2 + rb);
    float4 vv[V];
    float s = 0.f, s2 = 0.f;
#pragma unroll
    for (int i = 0; i < V; i++) {
        float4 a = ar[threadIdx.x + i * 256];
        float4 c = cr[threadIdx.x + i * 256];
        float4 t;
        t.x = a.x / (1.f + __expf(-a.x)) * c.x;
        t.y = a.y / (1.f + __expf(-a.y)) * c.y;
        t.z = a.z / (1.f + __expf(-a.z)) * c.z;
        t.w = a.w / (1.f + __expf(-a.w)) * c.w;
        vv[i] = t;
        s  += t.x + t.y + t.z + t.w;
        s2 += t.x*t.x + t.y*t.y + t.z*t.z + t.w*t.w;
    }
#pragma unroll
    for (int o = 16; o; o >>= 1) {
        s  += __shfl_xor_sync(0xffffffffu, s,  o);
        s2 += __shfl_xor_sync(0xffffffffu, s2, o);
    }
    if ((threadIdx.x & 31) == 0) { red0[threadIdx.x >> 5] = s; red1[threadIdx.x >> 5] = s2; }
    __syncthreads();
    if (threadIdx.x == 0) {
        float a = 0.f, c = 0.f;
#pragma unroll
        for (int i = 0; i < 8; i++) { a += red0[i]; c += red1[i]; }
        float mu  = a / (float)W;
        float var = c / (float)W - mu * mu;
        stats[0] = mu;
        stats[1] = rsqrtf(var + LN_EPS);
    }
    __syncthreads();
    float mu = stats[0], inv = stats[1];
    float4* yr = (float4*)(h1 + rb);
    const float4* g4 = (const float4*)g;
    const float4* b4 = (const float4*)b;
#pragma unroll
    for (int i = 0; i < V; i++) {
        int c = threadIdx.x + i * 256;
        float4 gg = g4[c], bb = b4[c], t = vv[i], o;
        o.x = (t.x - mu) * inv * gg.x + bb.x;
        o.y = (t.y - mu) * inv * gg.y + bb.y;
        o.z = (t.z - mu) * inv * gg.z + bb.z;
        o.w = (t.w - mu) * inv * gg.w + bb.w;
        yr[c] = o;
    }
}

// ---------------- RoPE on q,k (skip token 0); scale q by hd^-0.5 ------------
__global__ void __launch_bounds__(256) rope_kernel(float* __restrict__ q,
                                                   float* __restrict__ k,
                                                   const float* __restrict__ cosb,
                                                   const float* __restrict__ sinb)
{
    const float scale = 0.125f;   // 64^-0.5
    int row = blockIdx.x;
    int n = row % NTOK;
    size_t rb = (size_t)row * DMODEL;
    float4* qr = (float4*)(q + rb);
    float4* kr = (float4*)(k + rb);
    int ci = threadIdx.x;                 // float4 index, col = 4*ci
    if (n == 0) {
        float4 t = qr[ci];
        t.x *= scale; t.y *= scale; t.z *= scale; t.w *= scale;
        qr[ci] = t;
        return;
    }
    int d = (ci * 4) & 63;                // position within head, multiple of 4
    const float4 cs = *(const float4*)(cosb + (size_t)(n - 1) * HD + d);
    const float4 sn = *(const float4*)(sinb + (size_t)(n - 1) * HD + d);
    float4 t = qr[ci], o;
    o.x = t.x * cs.x - t.y * sn.x;
    o.y = t.y * cs.y + t.x * sn.y;
    o.z = t.z * cs.z - t.w * sn.z;
    o.w = t.w * cs.w + t.z * sn.w;
    o.x *= scale; o.y *= scale; o.z *= scale; o.w *= scale;
    qr[ci] = o;
    t = kr[ci];
    o.x = t.x * cs.x - t.y * sn.x;
    o.y = t.y * cs.y + t.x * sn.y;
    o.z = t.z * cs.z - t.w * sn.z;
    o.w = t.w * cs.w + t.z * sn.w;
    kr[ci] = o;
}

// ---------------- fused attention: one block per (b,h) ----------------------
// smem: Ks[257*65] Vs[257*65] bias[964] p[8*264] qrow[8*64]
#define ATTN_SMEM_FLOATS (2 * 257 * 65 + 964 + 8 * 264 + 8 * 64)
__global__ void __launch_bounds__(256) attn_kernel(const float* __restrict__ q,
                                                   const float* __restrict__ k,
                                                   const float* __restrict__ v,
                                                   const float* __restrict__ table,
                                                   float* __restrict__ out)
{
    extern __shared__ float sm[];
    float* Ks = sm;
    float* Vs = Ks + 257 * 65;
    float* bs = Vs + 257 * 65;
    float* ps = bs + 964;
    float* qs = ps + 8 * 264;

    int bh = blockIdx.x;
    int b = bh >> 4, h = bh & 15;
    int tid = threadIdx.x, lane = tid & 31, w = tid >> 5;
    size_t base = (size_t)b * NTOK * DMODEL + (size_t)h * HD;

    for (int i = tid; i < NTOK * HD; i += 256) {
        int r = i >> 6, c = i & 63;
        Ks[r * 65 + c] = k[base + (size_t)r * DMODEL + c];
        Vs[r * 65 + c] = v[base + (size_t)r * DMODEL + c];
    }
    for (int i = tid; i < 964; i += 256) bs[i] = table[(size_t)i * NHEAD + h];
    __syncthreads();

    for (int qi = w; qi < NTOK; qi += 8) {
        qs[w * 64 + lane]      = q[base + (size_t)qi * DMODEL + lane];
        qs[w * 64 + lane + 32] = q[base + (size_t)qi * DMODEL + lane + 32];
        __syncwarp();
        int pq = qi - 1, chq = pq >> 4, cwq = pq & 15;
        float e[9];
        float mx = -1e30f;
#pragma unroll
        for (int j = 0; j < 9; j++) {
            int kk = j * 32 + lane;
            float sc = -1e30f;
            if (kk < NTOK) {
                const float* krow = &Ks[kk * 65];
                const float* qrow = &qs[w * 64];
                float dot = 0.f;
#pragma unroll
                for (int d2 = 0; d2 < 64; d2++) dot += qrow[d2] * krow[d2];
                int idx;
                if (qi == 0 && kk == 0)      idx = 963;
                else if (qi == 0)            idx = 961;
                else if (kk == 0)            idx = 962;
                else {
                    int pk = kk - 1;
                    idx = (chq - (pk >> 4) + 15) * 31 + (cwq - (pk & 15) + 15);
                }
                sc = dot + bs[idx];
            }
            e[j] = sc;
            mx = fmaxf(mx, sc);
        }
#pragma unroll
        for (int o = 16; o; o >>= 1) mx = fmaxf(mx, __shfl_xor_sync(0xffffffffu, mx, o));
        float sum = 0.f;
#pragma unroll
        for (int j = 0; j < 9; j++) {
            e[j] = (e[j] > -1e29f) ? __expf(e[j] - mx) : 0.f;
            sum += e[j];
        }
#pragma unroll
        for (int o = 16; o; o >>= 1) sum += __shfl_xor_sync(0xffffffffu, sum, o);
        float inv = 1.f / sum;
        __syncwarp();   // previous iteration's ps reads are done
#pragma unroll
        for (int j = 0; j < 9; j++) {
            int kk = j * 32 + lane;
            if (kk < NTOK) ps[w * 264 + kk] = e[j] * inv;
        }
        __syncwarp();
        float a0 = 0.f, a1 = 0.f;
        const float* pp = &ps[w * 264];
        for (int kk = 0; kk < NTOK; kk++) {
            float pk = pp[kk];
            a0 += pk * Vs[kk * 65 + lane];
            a1 += pk * Vs[kk * 65 + lane + 32];
        }
        out[base + (size_t)qi * DMODEL + lane]      = a0;
        out[base + (size_t)qi * DMODEL + lane + 32] = a1;
    }
}

// ---------------- SGEMM-NT: C[m,n] = sum_k A[m,k]*B[n,k] + bias + res -------
// A: MxK row-major, B: NxK row-major (weight). 128x128x16 tiles, 256 threads.
template<bool RES>
__global__ void __launch_bounds__(256) sgemm_nt(const float* __restrict__ A,
                                                const float* __restrict__ Bw,
                                                const float* __restrict__ bias,
                                                const float* __restrict__ res,
                                                float* __restrict__ C,
                                                int M, int N, int K)
{
    __shared__ float As[16 * 128];
    __shared__ float Bs[16 * 128];
    int tid = threadIdx.x;
    int tx = tid & 15, ty = tid >> 4;
    int n0 = blockIdx.x * 128, m0 = blockIdx.y * 128;

    int lrow = tid >> 2;            // 0..63
    int lk4  = (tid & 3) * 4;       // 0,4,8,12

    float acc[8][8];
#pragma unroll
    for (int i = 0; i < 8; i++)
#pragma unroll
        for (int j = 0; j < 8; j++) acc[i][j] = 0.f;

    for (int k0 = 0; k0 < K; k0 += 16) {
#pragma unroll
        for (int it = 0; it < 2; it++) {
            int row = lrow + it * 64;
            int m = m0 + row;
            float4 av = (m < M) ? *(const float4*)&A[(size_t)m * K + k0 + lk4]
                                : make_float4(0.f, 0.f, 0.f, 0.f);
            As[(lk4 + 0) * 128 + row] = av.x;
            As[(lk4 + 1) * 128 + row] = av.y;
            As[(lk4 + 2) * 128 + row] = av.z;
            As[(lk4 + 3) * 128 + row] = av.w;
            int n = n0 + row;
            float4 bv = *(const float4*)&Bw[(size_t)n * K + k0 + lk4];
            Bs[(lk4 + 0) * 128 + row] = bv.x;
            Bs[(lk4 + 1) * 128 + row] = bv.y;
            Bs[(lk4 + 2) * 128 + row] = bv.z;
            Bs[(lk4 + 3) * 128 + row] = bv.w;
        }
        __syncthreads();
#pragma unroll
        for (int kk = 0; kk < 16; kk++) {
            float4 a0 = *(float4*)&As[kk * 128 + ty * 8];
            float4 a1 = *(float4*)&As[kk * 128 + ty * 8 + 4];
            float4 b0 = *(float4*)&Bs[kk * 128 + tx * 8];
            float4 b1 = *(float4*)&Bs[kk * 128 + tx * 8 + 4];
            float ar[8] = {a0.x, a0.y, a0.z, a0.w, a1.x, a1.y, a1.z, a1.w};
            float br[8] = {b0.x, b0.y, b0.z, b0.w, b1.x, b1.y, b1.z, b1.w};
#pragma unroll
            for (int i = 0; i < 8; i++)
#pragma unroll
                for (int j = 0; j < 8; j++) acc[i][j] += ar[i] * br[j];
        }
        __syncthreads();
    }

    float bj[8];
#pragma unroll
    for (int j = 0; j < 8; j++) bj[j] = bias ? bias[n0 + tx * 8 + j] : 0.f;

#pragma unroll
    for (int i = 0; i < 8; i++) {
        int m = m0 + ty * 8 + i;
        if (m < M) {
            size_t off = (size_t)m * N + n0 + tx * 8;
            float4 o0, o1;
            o0.x = acc[i][0] + bj[0]; o0.y = acc[i][1] + bj[1];
            o0.z = acc[i][2] + bj[2]; o0.w = acc[i][3] + bj[3];
            o1.x = acc[i][4] + bj[4]; o1.y = acc[i][5] + bj[5];
            o1.z = acc[i][6] + bj[6]; o1.w = acc[i][7] + bj[7];
            if (RES) {
                float4 r0 = *(const float4*)&res[off];
                float4 r1 = *(const float4*)&res[off + 4];
                o0.x += r0.x; o0.y += r0.y; o0.z += r0.z; o0.w += r0.w;
                o1.x += r1.x; o1.y += r1.y; o1.z += r1.z; o1.w += r1.w;
            }
            *(float4*)&C[off]     = o0;
            *(float4*)&C[off + 4] = o1;
        }
    }
}

// ---------------- launch --------------------------------------------------
extern "C" void kernel_launch(void* const* d_in, const int* in_sizes, int n_in,
                              void* d_out, int out_size)
{
    const float* x        = (const float*)d_in[0];
    const float* rope_cos = (const float*)d_in[1];
    const float* rope_sin = (const float*)d_in[2];
    const float* q_w      = (const float*)d_in[3];
    const float* q_b      = (const float*)d_in[4];
    const float* k_w      = (const float*)d_in[5];
    const float* v_w      = (const float*)d_in[6];
    const float* v_b      = (const float*)d_in[7];
    const float* table    = (const float*)d_in[8];
    const float* in_g     = (const float*)d_in[9];
    const float* in_b     = (const float*)d_in[10];
    const float* proj_w   = (const float*)d_in[11];
    const float* proj_b   = (const float*)d_in[12];
    const float* n1g      = (const float*)d_in[13];
    const float* n1b      = (const float*)d_in[14];
    const float* n2g      = (const float*)d_in[15];
    const float* n2b      = (const float*)d_in[16];
    const float* w1       = (const float*)d_in[17];
    const float* w1b      = (const float*)d_in[18];
    const float* w2       = (const float*)d_in[19];
    const float* w2b      = (const float*)d_in[20];
    const float* fg       = (const float*)d_in[21];
    const float* fb       = (const float*)d_in[22];
    const float* w3       = (const float*)d_in[23];
    const float* w3b      = (const float*)d_in[24];
    float* out = (float*)d_out;

    float *xn, *q, *k, *v, *att, *x1, *h1, *h2;
    cudaGetSymbolAddress((void**)&xn,  g_xn);
    cudaGetSymbolAddress((void**)&q,   g_q);
    cudaGetSymbolAddress((void**)&k,   g_k);
    cudaGetSymbolAddress((void**)&v,   g_v);
    cudaGetSymbolAddress((void**)&att, g_att);
    cudaGetSymbolAddress((void**)&x1,  g_x1);
    cudaGetSymbolAddress((void**)&h1,  g_h1);
    cudaGetSymbolAddress((void**)&h2,  g_h2);

    int attn_smem = ATTN_SMEM_FLOATS * 4;
    cudaFuncSetAttribute(attn_kernel, cudaFuncAttributeMaxDynamicSharedMemorySize, attn_smem);

    dim3 blk(256);
    dim3 gD((DMODEL + 127) / 128, (T_TOK + 127) / 128);   // (8, 129)
    dim3 gH((HDIM   + 127) / 128, (T_TOK + 127) / 128);   // (32, 129)

    // 1) norm1
    ln_kernel<DMODEL><<<T_TOK, blk>>>(x, n1g, n1b, xn);
    // 2) QKV projections
    sgemm_nt<false><<<gD, blk>>>(xn, q_w, q_b,   nullptr, q, T_TOK, DMODEL, DMODEL);
    sgemm_nt<false><<<gD, blk>>>(xn, k_w, nullptr, nullptr, k, T_TOK, DMODEL, DMODEL);
    sgemm_nt<false><<<gD, blk>>>(xn, v_w, v_b,   nullptr, v, T_TOK, DMODEL, DMODEL);
    // 3) RoPE + q scaling
    rope_kernel<<<T_TOK, blk>>>(q, k, rope_cos, rope_sin);
    // 4) attention
    attn_kernel<<<BATCH * NHEAD, blk, attn_smem>>>(q, k, v, table, att);
    // 5) inner LN, proj (+ residual with original x) -> x1
    ln_kernel<DMODEL><<<T_TOK, blk>>>(att, in_g, in_b, xn);
    sgemm_nt<true><<<gD, blk>>>(xn, proj_w, proj_b, x, x1, T_TOK, DMODEL, DMODEL);
    // 6) norm2
    ln_kernel<DMODEL><<<T_TOK, blk>>>(x1, n2g, n2b, xn);
    // 7) FFN up projections
    sgemm_nt<false><<<gH, blk>>>(xn, w1, w1b, nullptr, h1, T_TOK, HDIM, DMODEL);
    sgemm_nt<false><<<gH, blk>>>(xn, w2, w2b, nullptr, h2, T_TOK, HDIM, DMODEL);
    // 8) silu(h1)*h2 -> ffn LN (in place into h1)
    silu_ln_kernel<<<T_TOK, blk>>>(h1, h2, fg, fb);
    // 9) down projection + residual -> out
    sgemm_nt<true><<<gD, blk>>>(h1, w3, w3b, x1, out, T_TOK, DMODEL, HDIM);
}

// round 6
// speedup vs baseline: 2.4841x; 2.4841x over previous
#include <cuda_runtime.h>
#include <cuda_bf16.h>
#include <stdint.h>
#include <math.h>

#define NTOK   257
#define BATCH  64
#define T_TOK  (BATCH * NTOK)   // 16448
#define DMODEL 1024
#define NHEAD  16
#define HD     64
#define HDIM   4096
#define LN_EPS 1e-5f

// ---------------- scratch (device globals; no allocations allowed) ----------
__device__ __align__(16) float g_q  [(size_t)T_TOK * DMODEL];
__device__ __align__(16) float g_k  [(size_t)T_TOK * DMODEL];
__device__ __align__(16) float g_v  [(size_t)T_TOK * DMODEL];
__device__ __align__(16) float g_att[(size_t)T_TOK * DMODEL];
__device__ __align__(16) float g_x1 [(size_t)T_TOK * DMODEL];
__device__ __align__(16) float g_h1 [(size_t)T_TOK * HDIM];
__device__ __align__(16) float g_h2 [(size_t)T_TOK * HDIM];

// bf16 hi/lo planes
__device__ __align__(16) __nv_bfloat16 g_ah[(size_t)T_TOK * DMODEL];
__device__ __align__(16) __nv_bfloat16 g_al[(size_t)T_TOK * DMODEL];
__device__ __align__(16) __nv_bfloat16 g_hh[(size_t)T_TOK * HDIM];
__device__ __align__(16) __nv_bfloat16 g_hl[(size_t)T_TOK * HDIM];
__device__ __align__(16) __nv_bfloat16 g_qwh[(size_t)DMODEL * DMODEL], g_qwl[(size_t)DMODEL * DMODEL];
__device__ __align__(16) __nv_bfloat16 g_kwh[(size_t)DMODEL * DMODEL], g_kwl[(size_t)DMODEL * DMODEL];
__device__ __align__(16) __nv_bfloat16 g_vwh[(size_t)DMODEL * DMODEL], g_vwl[(size_t)DMODEL * DMODEL];
__device__ __align__(16) __nv_bfloat16 g_pwh[(size_t)DMODEL * DMODEL], g_pwl[(size_t)DMODEL * DMODEL];
__device__ __align__(16) __nv_bfloat16 g_w1h[(size_t)HDIM * DMODEL],  g_w1l[(size_t)HDIM * DMODEL];
__device__ __align__(16) __nv_bfloat16 g_w2h[(size_t)HDIM * DMODEL],  g_w2l[(size_t)HDIM * DMODEL];
__device__ __align__(16) __nv_bfloat16 g_w3h[(size_t)DMODEL * HDIM],  g_w3l[(size_t)DMODEL * HDIM];

// ---------------- fp32 -> bf16 hi/lo helpers ---------------------------------
__device__ __forceinline__ void cvt4(float4 t, uint2& hp, uint2& lp)
{
    __nv_bfloat16 h0 = __float2bfloat16(t.x);
    __nv_bfloat16 h1 = __float2bfloat16(t.y);
    __nv_bfloat16 h2 = __float2bfloat16(t.z);
    __nv_bfloat16 h3 = __float2bfloat16(t.w);
    __nv_bfloat16 l0 = __float2bfloat16(t.x - __bfloat162float(h0));
    __nv_bfloat16 l1 = __float2bfloat16(t.y - __bfloat162float(h1));
    __nv_bfloat16 l2 = __float2bfloat16(t.z - __bfloat162float(h2));
    __nv_bfloat16 l3 = __float2bfloat16(t.w - __bfloat162float(h3));
    __nv_bfloat162 a = __halves2bfloat162(h0, h1);
    __nv_bfloat162 b = __halves2bfloat162(h2, h3);
    __nv_bfloat162 c = __halves2bfloat162(l0, l1);
    __nv_bfloat162 d = __halves2bfloat162(l2, l3);
    hp.x = *(uint32_t*)&a; hp.y = *(uint32_t*)&b;
    lp.x = *(uint32_t*)&c; lp.y = *(uint32_t*)&d;
}

__global__ void __launch_bounds__(256) cvt_hl(const float* __restrict__ x,
                                              __nv_bfloat16* __restrict__ hi,
                                              __nv_bfloat16* __restrict__ lo,
                                              int n4)
{
    int i = blockIdx.x * 256 + threadIdx.x;
    if (i >= n4) return;
    float4 v = ((const float4*)x)[i];
    uint2 hp, lp;
    cvt4(v, hp, lp);
    ((uint2*)hi)[i] = hp;
    ((uint2*)lo)[i] = lp;
}

// ---------------- mma.sync GEMM: C = A*B^T (+bias)(+res), fp32 out ----------
// A,B as bf16 hi/lo planes, K-major row-major. CTA 128x128, K chunk 32,
// 8 warps (2x4), warp tile 64x32, double-buffered cp.async.
#define RSB   80          // smem row stride in bytes (40 bf16)
#define PLANE 10240       // 128 rows * 80B
#define BUFSZ (4 * PLANE) // Ah, Al, Bh, Bl
#define SMEM_G (2 * BUFSZ)

#define LDSM4(r0, r1, r2, r3, addr) \
    asm volatile("ldmatrix.sync.aligned.m8n8.x4.shared.b16 {%0,%1,%2,%3}, [%4];" \
                 : "=r"(r0), "=r"(r1), "=r"(r2), "=r"(r3) : "r"(addr))

#define MMA16816(c, a, b) \
    asm volatile("mma.sync.aligned.m16n8k16.row.col.f32.bf16.bf16.f32 " \
                 "{%0,%1,%2,%3}, {%4,%5,%6,%7}, {%8,%9}, {%0,%1,%2,%3};" \
                 : "+f"((c)[0]), "+f"((c)[1]), "+f"((c)[2]), "+f"((c)[3]) \
                 : "r"((a)[0]), "r"((a)[1]), "r"((a)[2]), "r"((a)[3]), \
                   "r"((b)[0]), "r"((b)[1]))

template<bool RES>
__global__ void __launch_bounds__(256) tgemm(const __nv_bfloat16* __restrict__ Ah,
                                             const __nv_bfloat16* __restrict__ Al,
                                             const __nv_bfloat16* __restrict__ Bh,
                                             const __nv_bfloat16* __restrict__ Bl,
                                             const float* __restrict__ bias,
                                             const float* __restrict__ res,
                                             float* __restrict__ C,
                                             int M, int N, int K)
{
    extern __shared__ __align__(16) char dsm[];
    uint32_t sb = (uint32_t)__cvta_generic_to_shared(dsm);

    int tid = threadIdx.x, lane = tid & 31, warp = tid >> 5;
    int wm = warp >> 2, wn = warp & 3;           // warp grid 2 x 4
    int m0 = blockIdx.y * 128, n0 = blockIdx.x * 128;

    float acc[4][4][4];
#pragma unroll
    for (int i = 0; i < 4; i++)
#pragma unroll
        for (int j = 0; j < 4; j++)
#pragma unroll
            for (int r = 0; r < 4; r++) acc[i][j][r] = 0.f;

    auto issue_loads = [&](int c) {
        int k0 = c * 32;
        uint32_t sbuf = sb + (uint32_t)(c & 1) * BUFSZ;
#pragma unroll
        for (int i = 0; i < 8; i++) {
            int gi = i * 256 + tid;
            int p = gi >> 9;                 // plane 0:Ah 1:Al 2:Bh 3:Bl
            int idx = gi & 511;
            int row = idx >> 2, cc = idx & 3;
            const __nv_bfloat16* gp = (p == 0) ? Ah : (p == 1) ? Al : (p == 2) ? Bh : Bl;
            int grow = ((p < 2) ? m0 : n0) + row;
            int sz = 16;
            if (p < 2 && grow >= M) { grow = 0; sz = 0; }
            const void* src = gp + (size_t)grow * K + k0 + cc * 8;
            uint32_t dst = sbuf + (uint32_t)p * PLANE + (uint32_t)(row * RSB + cc * 16);
            asm volatile("cp.async.ca.shared.global [%0], [%1], 16, %2;"
                         :: "r"(dst), "l"(src), "r"(sz));
        }
        asm volatile("cp.async.commit_group;" ::: "memory");
    };

    int KT = K >> 5;
    issue_loads(0);

    for (int c = 0; c < KT; c++) {
        if (c + 1 < KT) {
            issue_loads(c + 1);
            asm volatile("cp.async.wait_group 1;" ::: "memory");
        } else {
            asm volatile("cp.async.wait_group 0;" ::: "memory");
        }
        __syncthreads();

        uint32_t sbuf = sb + (uint32_t)(c & 1) * BUFSZ;
#pragma unroll
        for (int kk = 0; kk < 32; kk += 16) {
            uint32_t ah[4][4], al_[4][4], bh[4][2], bl[4][2];
            // A fragments (hi & lo)
#pragma unroll
            for (int mi = 0; mi < 4; mi++) {
                int arow = wm * 64 + mi * 16 + (lane & 15);
                uint32_t aoff = (uint32_t)(arow * RSB + (kk + (lane >> 4) * 8) * 2);
                uint32_t a0 = sbuf + 0 * PLANE + aoff;
                LDSM4(ah[mi][0], ah[mi][1], ah[mi][2], ah[mi][3], a0);
                uint32_t a1 = sbuf + 1 * PLANE + aoff;
                LDSM4(al_[mi][0], al_[mi][1], al_[mi][2], al_[mi][3], a1);
            }
            // B fragments (hi & lo): x4 covers two n8 blocks
#pragma unroll
            for (int nj = 0; nj < 2; nj++) {
                int g = lane >> 3;
                int nrow = wn * 32 + nj * 16 + (g >> 1) * 8 + (lane & 7);
                uint32_t boff = (uint32_t)(nrow * RSB + (kk + (g & 1) * 8) * 2);
                uint32_t b0 = sbuf + 2 * PLANE + boff;
                LDSM4(bh[nj*2][0], bh[nj*2][1], bh[nj*2+1][0], bh[nj*2+1][1], b0);
                uint32_t b1 = sbuf + 3 * PLANE + boff;
                LDSM4(bl[nj*2][0], bl[nj*2][1], bl[nj*2+1][0], bl[nj*2+1][1], b1);
            }
            // pass-major MMA: acc reuse 16 apart (no RAW stalls)
#pragma unroll
            for (int mi = 0; mi < 4; mi++)
#pragma unroll
                for (int ni = 0; ni < 4; ni++)
                    MMA16816(acc[mi][ni], ah[mi], bh[ni]);
#pragma unroll
            for (int mi = 0; mi < 4; mi++)
#pragma unroll
                for (int ni = 0; ni < 4; ni++)
                    MMA16816(acc[mi][ni], al_[mi], bh[ni]);
#pragma unroll
            for (int mi = 0; mi < 4; mi++)
#pragma unroll
                for (int ni = 0; ni < 4; ni++)
                    MMA16816(acc[mi][ni], ah[mi], bl[ni]);
        }
        __syncthreads();
    }

    // epilogue
#pragma unroll
    for (int mi = 0; mi < 4; mi++) {
#pragma unroll
        for (int ni = 0; ni < 4; ni++) {
            int r0 = m0 + wm * 64 + mi * 16 + (lane >> 2);
            int col = n0 + wn * 32 + ni * 8 + (lane & 3) * 2;
            float bx = 0.f, by = 0.f;
            if (bias) { bx = bias[col]; by = bias[col + 1]; }
            float2 v0, v1;
            v0.x = acc[mi][ni][0] + bx; v0.y = acc[mi][ni][1] + by;
            v1.x = acc[mi][ni][2] + bx; v1.y = acc[mi][ni][3] + by;
            if (r0 < M) {
                size_t off = (size_t)r0 * N + col;
                if (RES) { float2 rr = *(const float2*)&res[off]; v0.x += rr.x; v0.y += rr.y; }
                *(float2*)&C[off] = v0;
            }
            if (r0 + 8 < M) {
                size_t off = (size_t)(r0 + 8) * N + col;
                if (RES) { float2 rr = *(const float2*)&res[off]; v1.x += rr.x; v1.y += rr.y; }
                *(float2*)&C[off] = v1;
            }
        }
    }
}

// ---------------- LayerNorm -> bf16 hi/lo planes -----------------------------
template<int W>
__global__ void __launch_bounds__(256) ln_hl(const float* __restrict__ x,
                                             const float* __restrict__ g,
                                             const float* __restrict__ b,
                                             __nv_bfloat16* __restrict__ oh,
                                             __nv_bfloat16* __restrict__ ol)
{
    constexpr int V = W / 1024;
    __shared__ float red0[8], red1[8];
    __shared__ float stats[2];
    size_t rb = (size_t)blockIdx.x * W;
    const float4* xr = (const float4*)(x + rb);
    float4 vv[V];
    float s = 0.f, s2 = 0.f;
#pragma unroll
    for (int i = 0; i < V; i++) {
        float4 t = xr[threadIdx.x + i * 256];
        vv[i] = t;
        s  += t.x + t.y + t.z + t.w;
        s2 += t.x*t.x + t.y*t.y + t.z*t.z + t.w*t.w;
    }
#pragma unroll
    for (int o = 16; o; o >>= 1) {
        s  += __shfl_xor_sync(0xffffffffu, s,  o);
        s2 += __shfl_xor_sync(0xffffffffu, s2, o);
    }
    if ((threadIdx.x & 31) == 0) { red0[threadIdx.x >> 5] = s; red1[threadIdx.x >> 5] = s2; }
    __syncthreads();
    if (threadIdx.x == 0) {
        float a = 0.f, c = 0.f;
#pragma unroll
        for (int i = 0; i < 8; i++) { a += red0[i]; c += red1[i]; }
        float mu  = a / (float)W;
        float var = c / (float)W - mu * mu;
        stats[0] = mu;
        stats[1] = rsqrtf(var + LN_EPS);
    }
    __syncthreads();
    float mu = stats[0], inv = stats[1];
    const float4* g4 = (const float4*)g;
    const float4* b4 = (const float4*)b;
#pragma unroll
    for (int i = 0; i < V; i++) {
        int c = threadIdx.x + i * 256;
        float4 gg = g4[c], bb = b4[c], t = vv[i], o;
        o.x = (t.x - mu) * inv * gg.x + bb.x;
        o.y = (t.y - mu) * inv * gg.y + bb.y;
        o.z = (t.z - mu) * inv * gg.z + bb.z;
        o.w = (t.w - mu) * inv * gg.w + bb.w;
        uint2 hp, lp;
        cvt4(o, hp, lp);
        ((uint2*)(oh + rb))[c] = hp;
        ((uint2*)(ol + rb))[c] = lp;
    }
}

// ---------------- fused SiLU(h1)*h2 -> LayerNorm -> hi/lo planes ------------
__global__ void __launch_bounds__(256) silu_ln_hl(const float* __restrict__ h1,
                                                  const float* __restrict__ h2,
                                                  const float* __restrict__ g,
                                                  const float* __restrict__ b,
                                                  __nv_bfloat16* __restrict__ oh,
                                                  __nv_bfloat16* __restrict__ ol)
{
    constexpr int W = HDIM;
    constexpr int V = W / 1024;
    __shared__ float red0[8], red1[8];
    __shared__ float stats[2];
    size_t rb = (size_t)blockIdx.x * W;
    const float4* ar = (const float4*)(h1 + rb);
    const float4* cr = (const float4*)(h2 + rb);
    float4 vv[V];
    float s = 0.f, s2 = 0.f;
#pragma unroll
    for (int i = 0; i < V; i++) {
        float4 a = ar[threadIdx.x + i * 256];
        float4 c = cr[threadIdx.x + i * 256];
        float4 t;
        t.x = a.x / (1.f + __expf(-a.x)) * c.x;
        t.y = a.y / (1.f + __expf(-a.y)) * c.y;
        t.z = a.z / (1.f + __expf(-a.z)) * c.z;
        t.w = a.w / (1.f + __expf(-a.w)) * c.w;
        vv[i] = t;
        s  += t.x + t.y + t.z + t.w;
        s2 += t.x*t.x + t.y*t.y + t.z*t.z + t.w*t.w;
    }
#pragma unroll
    for (int o = 16; o; o >>= 1) {
        s  += __shfl_xor_sync(0xffffffffu, s,  o);
        s2 += __shfl_xor_sync(0xffffffffu, s2, o);
    }
    if ((threadIdx.x & 31) == 0) { red0[threadIdx.x >> 5] = s; red1[threadIdx.x >> 5] = s2; }
    __syncthreads();
    if (threadIdx.x == 0) {
        float a = 0.f, c = 0.f;
#pragma unroll
        for (int i = 0; i < 8; i++) { a += red0[i]; c += red1[i]; }
        float mu  = a / (float)W;
        float var = c / (float)W - mu * mu;
        stats[0] = mu;
        stats[1] = rsqrtf(var + LN_EPS);
    }
    __syncthreads();
    float mu = stats[0], inv = stats[1];
    const float4* g4 = (const float4*)g;
    const float4* b4 = (const float4*)b;
#pragma unroll
    for (int i = 0; i < V; i++) {
        int c = threadIdx.x + i * 256;
        float4 gg = g4[c], bb = b4[c], t = vv[i], o;
        o.x = (t.x - mu) * inv * gg.x + bb.x;
        o.y = (t.y - mu) * inv * gg.y + bb.y;
        o.z = (t.z - mu) * inv * gg.z + bb.z;
        o.w = (t.w - mu) * inv * gg.w + bb.w;
        uint2 hp, lp;
        cvt4(o, hp, lp);
        ((uint2*)(oh + rb))[c] = hp;
        ((uint2*)(ol + rb))[c] = lp;
    }
}

// ---------------- RoPE on q,k (skip token 0); scale q by hd^-0.5 ------------
__global__ void __launch_bounds__(256) rope_kernel(float* __restrict__ q,
                                                   float* __restrict__ k,
                                                   const float* __restrict__ cosb,
                                                   const float* __restrict__ sinb)
{
    const float scale = 0.125f;
    int row = blockIdx.x;
    int n = row % NTOK;
    size_t rb = (size_t)row * DMODEL;
    float4* qr = (float4*)(q + rb);
    float4* kr = (float4*)(k + rb);
    int ci = threadIdx.x;
    if (n == 0) {
        float4 t = qr[ci];
        t.x *= scale; t.y *= scale; t.z *= scale; t.w *= scale;
        qr[ci] = t;
        return;
    }
    int d = (ci * 4) & 63;
    const float4 cs = *(const float4*)(cosb + (size_t)(n - 1) * HD + d);
    const float4 sn = *(const float4*)(sinb + (size_t)(n - 1) * HD + d);
    float4 t = qr[ci], o;
    o.x = t.x * cs.x - t.y * sn.x;
    o.y = t.y * cs.y + t.x * sn.y;
    o.z = t.z * cs.z - t.w * sn.z;
    o.w = t.w * cs.w + t.z * sn.w;
    o.x *= scale; o.y *= scale; o.z *= scale; o.w *= scale;
    qr[ci] = o;
    t = kr[ci];
    o.x = t.x * cs.x - t.y * sn.x;
    o.y = t.y * cs.y + t.x * sn.y;
    o.z = t.z * cs.z - t.w * sn.z;
    o.w = t.w * cs.w + t.z * sn.w;
    kr[ci] = o;
}

// ---------------- fused attention: one block per (b,h) ----------------------
#define ATTN_SMEM_FLOATS (2 * 257 * 65 + 964 + 8 * 264 + 8 * 64)
__global__ void __launch_bounds__(256) attn_kernel(const float* __restrict__ q,
                                                   const float* __restrict__ k,
                                                   const float* __restrict__ v,
                                                   const float* __restrict__ table,
                                                   float* __restrict__ out)
{
    extern __shared__ float sm[];
    float* Ks = sm;
    float* Vs = Ks + 257 * 65;
    float* bs = Vs + 257 * 65;
    float* ps = bs + 964;
    float* qs = ps + 8 * 264;

    int bh = blockIdx.x;
    int b = bh >> 4, h = bh & 15;
    int tid = threadIdx.x, lane = tid & 31, w = tid >> 5;
    size_t base = (size_t)b * NTOK * DMODEL + (size_t)h * HD;

    for (int i = tid; i < NTOK * HD; i += 256) {
        int r = i >> 6, c = i & 63;
        Ks[r * 65 + c] = k[base + (size_t)r * DMODEL + c];
        Vs[r * 65 + c] = v[base + (size_t)r * DMODEL + c];
    }
    for (int i = tid; i < 964; i += 256) bs[i] = table[(size_t)i * NHEAD + h];
    __syncthreads();

    for (int qi = w; qi < NTOK; qi += 8) {
        qs[w * 64 + lane]      = q[base + (size_t)qi * DMODEL + lane];
        qs[w * 64 + lane + 32] = q[base + (size_t)qi * DMODEL + lane + 32];
        __syncwarp();
        int pq = qi - 1, chq = pq >> 4, cwq = pq & 15;
        float e[9];
        float mx = -1e30f;
#pragma unroll
        for (int j = 0; j < 9; j++) {
            int kk = j * 32 + lane;
            float sc = -1e30f;
            if (kk < NTOK) {
                const float* krow = &Ks[kk * 65];
                const float* qrow = &qs[w * 64];
                float dot = 0.f;
#pragma unroll
                for (int d2 = 0; d2 < 64; d2++) dot += qrow[d2] * krow[d2];
                int idx;
                if (qi == 0 && kk == 0)      idx = 963;
                else if (qi == 0)            idx = 961;
                else if (kk == 0)            idx = 962;
                else {
                    int pk = kk - 1;
                    idx = (chq - (pk >> 4) + 15) * 31 + (cwq - (pk & 15) + 15);
                }
                sc = dot + bs[idx];
            }
            e[j] = sc;
            mx = fmaxf(mx, sc);
        }
#pragma unroll
        for (int o = 16; o; o >>= 1) mx = fmaxf(mx, __shfl_xor_sync(0xffffffffu, mx, o));
        float sum = 0.f;
#pragma unroll
        for (int j = 0; j < 9; j++) {
            e[j] = (e[j] > -1e29f) ? __expf(e[j] - mx) : 0.f;
            sum += e[j];
        }
#pragma unroll
        for (int o = 16; o; o >>= 1) sum += __shfl_xor_sync(0xffffffffu, sum, o);
        float inv = 1.f / sum;
        __syncwarp();
#pragma unroll
        for (int j = 0; j < 9; j++) {
            int kk = j * 32 + lane;
            if (kk < NTOK) ps[w * 264 + kk] = e[j] * inv;
        }
        __syncwarp();
        float a0 = 0.f, a1 = 0.f;
        const float* pp = &ps[w * 264];
        for (int kk = 0; kk < NTOK; kk++) {
            float pk = pp[kk];
            a0 += pk * Vs[kk * 65 + lane];
            a1 += pk * Vs[kk * 65 + lane + 32];
        }
        out[base + (size_t)qi * DMODEL + lane]      = a0;
        out[base + (size_t)qi * DMODEL + lane + 32] = a1;
    }
}

// ---------------- launch -----------------------------------------------------
extern "C" void kernel_launch(void* const* d_in, const int* in_sizes, int n_in,
                              void* d_out, int out_size)
{
    const float* x        = (const float*)d_in[0];
    const float* rope_cos = (const float*)d_in[1];
    const float* rope_sin = (const float*)d_in[2];
    const float* q_w      = (const float*)d_in[3];
    const float* q_b      = (const float*)d_in[4];
    const float* k_w      = (const float*)d_in[5];
    const float* v_w      = (const float*)d_in[6];
    const float* v_b      = (const float*)d_in[7];
    const float* table    = (const float*)d_in[8];
    const float* in_g     = (const float*)d_in[9];
    const float* in_b     = (const float*)d_in[10];
    const float* proj_w   = (const float*)d_in[11];
    const float* proj_b   = (const float*)d_in[12];
    const float* n1g      = (const float*)d_in[13];
    const float* n1b      = (const float*)d_in[14];
    const float* n2g      = (const float*)d_in[15];
    const float* n2b      = (const float*)d_in[16];
    const float* w1       = (const float*)d_in[17];
    const float* w1b      = (const float*)d_in[18];
    const float* w2       = (const float*)d_in[19];
    const float* w2b      = (const float*)d_in[20];
    const float* fg       = (const float*)d_in[21];
    const float* fb       = (const float*)d_in[22];
    const float* w3       = (const float*)d_in[23];
    const float* w3b      = (const float*)d_in[24];
    float* out = (float*)d_out;

    float *q, *k, *v, *att, *x1, *h1, *h2;
    __nv_bfloat16 *ah, *al, *hh, *hl;
    __nv_bfloat16 *qwh, *qwl, *kwh, *kwl, *vwh, *vwl, *pwh, *pwl;
    __nv_bfloat16 *w1h, *w1l, *w2h, *w2l, *w3h, *w3l;
    cudaGetSymbolAddress((void**)&q,   g_q);
    cudaGetSymbolAddress((void**)&k,   g_k);
    cudaGetSymbolAddress((void**)&v,   g_v);
    cudaGetSymbolAddress((void**)&att, g_att);
    cudaGetSymbolAddress((void**)&x1,  g_x1);
    cudaGetSymbolAddress((void**)&h1,  g_h1);
    cudaGetSymbolAddress((void**)&h2,  g_h2);
    cudaGetSymbolAddress((void**)&ah,  g_ah);
    cudaGetSymbolAddress((void**)&al,  g_al);
    cudaGetSymbolAddress((void**)&hh,  g_hh);
    cudaGetSymbolAddress((void**)&hl,  g_hl);
    cudaGetSymbolAddress((void**)&qwh, g_qwh); cudaGetSymbolAddress((void**)&qwl, g_qwl);
    cudaGetSymbolAddress((void**)&kwh, g_kwh); cudaGetSymbolAddress((void**)&kwl, g_kwl);
    cudaGetSymbolAddress((void**)&vwh, g_vwh); cudaGetSymbolAddress((void**)&vwl, g_vwl);
    cudaGetSymbolAddress((void**)&pwh, g_pwh); cudaGetSymbolAddress((void**)&pwl, g_pwl);
    cudaGetSymbolAddress((void**)&w1h, g_w1h); cudaGetSymbolAddress((void**)&w1l, g_w1l);
    cudaGetSymbolAddress((void**)&w2h, g_w2h); cudaGetSymbolAddress((void**)&w2l, g_w2l);
    cudaGetSymbolAddress((void**)&w3h, g_w3h); cudaGetSymbolAddress((void**)&w3l, g_w3l);

    int attn_smem = ATTN_SMEM_FLOATS * 4;
    cudaFuncSetAttribute(attn_kernel, cudaFuncAttributeMaxDynamicSharedMemorySize, attn_smem);
    cudaFuncSetAttribute(tgemm<false>, cudaFuncAttributeMaxDynamicSharedMemorySize, SMEM_G);
    cudaFuncSetAttribute(tgemm<true>,  cudaFuncAttributeMaxDynamicSharedMemorySize, SMEM_G);

    dim3 blk(256);
    dim3 gD(DMODEL / 128, (T_TOK + 127) / 128);   // (8, 129)
    dim3 gH(HDIM / 128,   (T_TOK + 127) / 128);   // (32, 129)

    // 0) weight hi/lo conversions
    const int n4_1M = DMODEL * DMODEL / 4;        // 262144
    const int n4_4M = HDIM * DMODEL / 4;          // 1048576
    cvt_hl<<<(n4_1M + 255) / 256, blk>>>(q_w,    qwh, qwl, n4_1M);
    cvt_hl<<<(n4_1M + 255) / 256, blk>>>(k_w,    kwh, kwl, n4_1M);
    cvt_hl<<<(n4_1M + 255) / 256, blk>>>(v_w,    vwh, vwl, n4_1M);
    cvt_hl<<<(n4_1M + 255) / 256, blk>>>(proj_w, pwh, pwl, n4_1M);
    cvt_hl<<<(n4_4M + 255) / 256, blk>>>(w1,     w1h, w1l, n4_4M);
    cvt_hl<<<(n4_4M + 255) / 256, blk>>>(w2,     w2h, w2l, n4_4M);
    cvt_hl<<<(n4_4M + 255) / 256, blk>>>(w3,     w3h, w3l, n4_4M);

    // 1) norm1 -> hi/lo planes
    ln_hl<DMODEL><<<T_TOK, blk>>>(x, n1g, n1b, ah, al);
    // 2) QKV projections (tensor cores)
    tgemm<false><<<gD, blk, SMEM_G>>>(ah, al, qwh, qwl, q_b,     nullptr, q, T_TOK, DMODEL, DMODEL);
    tgemm<false><<<gD, blk, SMEM_G>>>(ah, al, kwh, kwl, nullptr, nullptr, k, T_TOK, DMODEL, DMODEL);
    tgemm<false><<<gD, blk, SMEM_G>>>(ah, al, vwh, vwl, v_b,     nullptr, v, T_TOK, DMODEL, DMODEL);
    // 3) RoPE + q scaling
    rope_kernel<<<T_TOK, blk>>>(q, k, rope_cos, rope_sin);
    // 4) attention
    attn_kernel<<<BATCH * NHEAD, blk, attn_smem>>>(q, k, v, table, att);
    // 5) inner LN -> planes, proj (+ residual with original x) -> x1
    ln_hl<DMODEL><<<T_TOK, blk>>>(att, in_g, in_b, ah, al);
    tgemm<true><<<gD, blk, SMEM_G>>>(ah, al, pwh, pwl, proj_b, x, x1, T_TOK, DMODEL, DMODEL);
    // 6) norm2 -> planes
    ln_hl<DMODEL><<<T_TOK, blk>>>(x1, n2g, n2b, ah, al);
    // 7) FFN up projections
    tgemm<false><<<gH, blk, SMEM_G>>>(ah, al, w1h, w1l, w1b, nullptr, h1, T_TOK, HDIM, DMODEL);
    tgemm<false><<<gH, blk, SMEM_G>>>(ah, al, w2h, w2l, w2b, nullptr, h2, T_TOK, HDIM, DMODEL);
    // 8) silu(h1)*h2 -> ffn LN -> hi/lo planes
    silu_ln_hl<<<T_TOK, blk>>>(h1, h2, fg, fb, hh, hl);
    // 9) down projection + residual -> out
    tgemm<true><<<gD, blk, SMEM_G>>>(hh, hl, w3h, w3l, w3b, x1, out, T_TOK, DMODEL, HDIM);
}

// round 7
// speedup vs baseline: 4.3031x; 1.7323x over previous
#include <cuda_runtime.h>
#include <cuda_fp16.h>
#include <stdint.h>
#include <math.h>

#define NTOK   257
#define BATCH  64
#define T_TOK  (BATCH * NTOK)   // 16448
#define DMODEL 1024
#define NHEAD  16
#define HD     64
#define HDIM   4096
#define LN_EPS 1e-5f

// ---------------- scratch (device globals; no allocations allowed) ----------
__device__ __align__(16) float g_q  [(size_t)T_TOK * DMODEL];
__device__ __align__(16) float g_k  [(size_t)T_TOK * DMODEL];
__device__ __align__(16) float g_v  [(size_t)T_TOK * DMODEL];
__device__ __align__(16) float g_att[(size_t)T_TOK * DMODEL];
__device__ __align__(16) float g_x1 [(size_t)T_TOK * DMODEL];
__device__ __align__(16) float g_h1 [(size_t)T_TOK * HDIM];
__device__ __align__(16) float g_h2 [(size_t)T_TOK * HDIM];

// fp16 planes
__device__ __align__(16) __half g_a16[(size_t)T_TOK * DMODEL];
__device__ __align__(16) __half g_h16[(size_t)T_TOK * HDIM];
__device__ __align__(16) __half g_qw16[(size_t)DMODEL * DMODEL];
__device__ __align__(16) __half g_kw16[(size_t)DMODEL * DMODEL];
__device__ __align__(16) __half g_vw16[(size_t)DMODEL * DMODEL];
__device__ __align__(16) __half g_pw16[(size_t)DMODEL * DMODEL];
__device__ __align__(16) __half g_w116[(size_t)HDIM * DMODEL];
__device__ __align__(16) __half g_w216[(size_t)HDIM * DMODEL];
__device__ __align__(16) __half g_w316[(size_t)DMODEL * HDIM];

// ---------------- fp32 -> fp16 helpers --------------------------------------
__device__ __forceinline__ uint2 pack16(float4 t)
{
    __half2 a = __floats2half2_rn(t.x, t.y);
    __half2 b = __floats2half2_rn(t.z, t.w);
    uint2 r;
    r.x = *(uint32_t*)&a;
    r.y = *(uint32_t*)&b;
    return r;
}

__global__ void __launch_bounds__(256) cvt16(const float* __restrict__ x,
                                             __half* __restrict__ o,
                                             int n4)
{
    int i = blockIdx.x * 256 + threadIdx.x;
    if (i >= n4) return;
    ((uint2*)o)[i] = pack16(((const float4*)x)[i]);
}

// ---------------- mma.sync GEMM: C = A*B^T (+bias)(+res), fp32 out ----------
// A,B fp16, K-major row-major. CTA 128x128, K chunk 32, 8 warps (2x4),
// warp tile 64x32, double-buffered cp.async.
#define RSB   80          // smem row stride in bytes (40 halves)
#define PLANE 10240       // 128 rows * 80B
#define BUFSZ (2 * PLANE) // A, B
#define SMEM_G (2 * BUFSZ)

#define LDSM4(r0, r1, r2, r3, addr) \
    asm volatile("ldmatrix.sync.aligned.m8n8.x4.shared.b16 {%0,%1,%2,%3}, [%4];" \
                 : "=r"(r0), "=r"(r1), "=r"(r2), "=r"(r3) : "r"(addr))

#define MMA16816(c, a, b) \
    asm volatile("mma.sync.aligned.m16n8k16.row.col.f32.f16.f16.f32 " \
                 "{%0,%1,%2,%3}, {%4,%5,%6,%7}, {%8,%9}, {%0,%1,%2,%3};" \
                 : "+f"((c)[0]), "+f"((c)[1]), "+f"((c)[2]), "+f"((c)[3]) \
                 : "r"((a)[0]), "r"((a)[1]), "r"((a)[2]), "r"((a)[3]), \
                   "r"((b)[0]), "r"((b)[1]))

template<bool RES>
__global__ void __launch_bounds__(256) tgemm(const __half* __restrict__ A,
                                             const __half* __restrict__ B,
                                             const float* __restrict__ bias,
                                             const float* __restrict__ res,
                                             float* __restrict__ C,
                                             int M, int N, int K)
{
    extern __shared__ __align__(16) char dsm[];
    uint32_t sb = (uint32_t)__cvta_generic_to_shared(dsm);

    int tid = threadIdx.x, lane = tid & 31, warp = tid >> 5;
    int wm = warp >> 2, wn = warp & 3;           // warp grid 2 x 4
    int m0 = blockIdx.y * 128, n0 = blockIdx.x * 128;

    float acc[4][4][4];
#pragma unroll
    for (int i = 0; i < 4; i++)
#pragma unroll
        for (int j = 0; j < 4; j++)
#pragma unroll
            for (int r = 0; r < 4; r++) acc[i][j][r] = 0.f;

    auto issue_loads = [&](int c) {
        int k0 = c * 32;
        uint32_t sbuf = sb + (uint32_t)(c & 1) * BUFSZ;
#pragma unroll
        for (int i = 0; i < 4; i++) {
            int gi = i * 256 + tid;
            int p = gi >> 9;                 // plane 0:A 1:B
            int idx = gi & 511;
            int row = idx >> 2, cc = idx & 3;
            const __half* gp = (p == 0) ? A : B;
            int grow = ((p == 0) ? m0 : n0) + row;
            int sz = 16;
            if (p == 0 && grow >= M) { grow = 0; sz = 0; }
            const void* src = gp + (size_t)grow * K + k0 + cc * 8;
            uint32_t dst = sbuf + (uint32_t)p * PLANE + (uint32_t)(row * RSB + cc * 16);
            asm volatile("cp.async.ca.shared.global [%0], [%1], 16, %2;"
                         :: "r"(dst), "l"(src), "r"(sz));
        }
        asm volatile("cp.async.commit_group;" ::: "memory");
    };

    int KT = K >> 5;
    issue_loads(0);

    for (int c = 0; c < KT; c++) {
        if (c + 1 < KT) {
            issue_loads(c + 1);
            asm volatile("cp.async.wait_group 1;" ::: "memory");
        } else {
            asm volatile("cp.async.wait_group 0;" ::: "memory");
        }
        __syncthreads();

        uint32_t sbuf = sb + (uint32_t)(c & 1) * BUFSZ;
#pragma unroll
        for (int kk = 0; kk < 32; kk += 16) {
            uint32_t af[4][4], bf[4][2];
#pragma unroll
            for (int mi = 0; mi < 4; mi++) {
                int arow = wm * 64 + mi * 16 + (lane & 15);
                uint32_t aoff = (uint32_t)(arow * RSB + (kk + (lane >> 4) * 8) * 2);
                LDSM4(af[mi][0], af[mi][1], af[mi][2], af[mi][3], sbuf + aoff);
            }
#pragma unroll
            for (int nj = 0; nj < 2; nj++) {
                int g = lane >> 3;
                int nrow = wn * 32 + nj * 16 + (g >> 1) * 8 + (lane & 7);
                uint32_t boff = (uint32_t)(nrow * RSB + (kk + (g & 1) * 8) * 2);
                LDSM4(bf[nj*2][0], bf[nj*2][1], bf[nj*2+1][0], bf[nj*2+1][1],
                      sbuf + PLANE + boff);
            }
#pragma unroll
            for (int mi = 0; mi < 4; mi++)
#pragma unroll
                for (int ni = 0; ni < 4; ni++)
                    MMA16816(acc[mi][ni], af[mi], bf[ni]);
        }
        __syncthreads();
    }

    // epilogue
#pragma unroll
    for (int mi = 0; mi < 4; mi++) {
#pragma unroll
        for (int ni = 0; ni < 4; ni++) {
            int r0 = m0 + wm * 64 + mi * 16 + (lane >> 2);
            int col = n0 + wn * 32 + ni * 8 + (lane & 3) * 2;
            float bx = 0.f, by = 0.f;
            if (bias) { bx = bias[col]; by = bias[col + 1]; }
            float2 v0, v1;
            v0.x = acc[mi][ni][0] + bx; v0.y = acc[mi][ni][1] + by;
            v1.x = acc[mi][ni][2] + bx; v1.y = acc[mi][ni][3] + by;
            if (r0 < M) {
                size_t off = (size_t)r0 * N + col;
                if (RES) { float2 rr = *(const float2*)&res[off]; v0.x += rr.x; v0.y += rr.y; }
                *(float2*)&C[off] = v0;
            }
            if (r0 + 8 < M) {
                size_t off = (size_t)(r0 + 8) * N + col;
                if (RES) { float2 rr = *(const float2*)&res[off]; v1.x += rr.x; v1.y += rr.y; }
                *(float2*)&C[off] = v1;
            }
        }
    }
}

// ---------------- LayerNorm -> fp16 plane ------------------------------------
template<int W>
__global__ void __launch_bounds__(256) ln16(const float* __restrict__ x,
                                            const float* __restrict__ g,
                                            const float* __restrict__ b,
                                            __half* __restrict__ o16)
{
    constexpr int V = W / 1024;
    __shared__ float red0[8], red1[8];
    __shared__ float stats[2];
    size_t rb = (size_t)blockIdx.x * W;
    const float4* xr = (const float4*)(x + rb);
    float4 vv[V];
    float s = 0.f, s2 = 0.f;
#pragma unroll
    for (int i = 0; i < V; i++) {
        float4 t = xr[threadIdx.x + i * 256];
        vv[i] = t;
        s  += t.x + t.y + t.z + t.w;
        s2 += t.x*t.x + t.y*t.y + t.z*t.z + t.w*t.w;
    }
#pragma unroll
    for (int o = 16; o; o >>= 1) {
        s  += __shfl_xor_sync(0xffffffffu, s,  o);
        s2 += __shfl_xor_sync(0xffffffffu, s2, o);
    }
    if ((threadIdx.x & 31) == 0) { red0[threadIdx.x >> 5] = s; red1[threadIdx.x >> 5] = s2; }
    __syncthreads();
    if (threadIdx.x == 0) {
        float a = 0.f, c = 0.f;
#pragma unroll
        for (int i = 0; i < 8; i++) { a += red0[i]; c += red1[i]; }
        float mu  = a / (float)W;
        float var = c / (float)W - mu * mu;
        stats[0] = mu;
        stats[1] = rsqrtf(var + LN_EPS);
    }
    __syncthreads();
    float mu = stats[0], inv = stats[1];
    const float4* g4 = (const float4*)g;
    const float4* b4 = (const float4*)b;
#pragma unroll
    for (int i = 0; i < V; i++) {
        int c = threadIdx.x + i * 256;
        float4 gg = g4[c], bb = b4[c], t = vv[i], o;
        o.x = (t.x - mu) * inv * gg.x + bb.x;
        o.y = (t.y - mu) * inv * gg.y + bb.y;
        o.z = (t.z - mu) * inv * gg.z + bb.z;
        o.w = (t.w - mu) * inv * gg.w + bb.w;
        ((uint2*)(o16 + rb))[c] = pack16(o);
    }
}

// ---------------- fused SiLU(h1)*h2 -> LayerNorm -> fp16 plane --------------
__global__ void __launch_bounds__(256) silu_ln16(const float* __restrict__ h1,
                                                 const float* __restrict__ h2,
                                                 const float* __restrict__ g,
                                                 const float* __restrict__ b,
                                                 __half* __restrict__ o16)
{
    constexpr int W = HDIM;
    constexpr int V = W / 1024;
    __shared__ float red0[8], red1[8];
    __shared__ float stats[2];
    size_t rb = (size_t)blockIdx.x * W;
    const float4* ar = (const float4*)(h1 + rb);
    const float4* cr = (const float4*)(h2 + rb);
    float4 vv[V];
    float s = 0.f, s2 = 0.f;
#pragma unroll
    for (int i = 0; i < V; i++) {
        float4 a = ar[threadIdx.x + i * 256];
        float4 c = cr[threadIdx.x + i * 256];
        float4 t;
        t.x = a.x / (1.f + __expf(-a.x)) * c.x;
        t.y = a.y / (1.f + __expf(-a.y)) * c.y;
        t.z = a.z / (1.f + __expf(-a.z)) * c.z;
        t.w = a.w / (1.f + __expf(-a.w)) * c.w;
        vv[i] = t;
        s  += t.x + t.y + t.z + t.w;
        s2 += t.x*t.x + t.y*t.y + t.z*t.z + t.w*t.w;
    }
#pragma unroll
    for (int o = 16; o; o >>= 1) {
        s  += __shfl_xor_sync(0xffffffffu, s,  o);
        s2 += __shfl_xor_sync(0xffffffffu, s2, o);
    }
    if ((threadIdx.x & 31) == 0) { red0[threadIdx.x >> 5] = s; red1[threadIdx.x >> 5] = s2; }
    __syncthreads();
    if (threadIdx.x == 0) {
        float a = 0.f, c = 0.f;
#pragma unroll
        for (int i = 0; i < 8; i++) { a += red0[i]; c += red1[i]; }
        float mu  = a / (float)W;
        float var = c / (float)W - mu * mu;
        stats[0] = mu;
        stats[1] = rsqrtf(var + LN_EPS);
    }
    __syncthreads();
    float mu = stats[0], inv = stats[1];
    const float4* g4 = (const float4*)g;
    const float4* b4 = (const float4*)b;
#pragma unroll
    for (int i = 0; i < V; i++) {
        int c = threadIdx.x + i * 256;
        float4 gg = g4[c], bb = b4[c], t = vv[i], o;
        o.x = (t.x - mu) * inv * gg.x + bb.x;
        o.y = (t.y - mu) * inv * gg.y + bb.y;
        o.z = (t.z - mu) * inv * gg.z + bb.z;
        o.w = (t.w - mu) * inv * gg.w + bb.w;
        ((uint2*)(o16 + rb))[c] = pack16(o);
    }
}

// ---------------- RoPE on q,k (skip token 0); scale q by hd^-0.5 ------------
__global__ void __launch_bounds__(256) rope_kernel(float* __restrict__ q,
                                                   float* __restrict__ k,
                                                   const float* __restrict__ cosb,
                                                   const float* __restrict__ sinb)
{
    const float scale = 0.125f;
    int row = blockIdx.x;
    int n = row % NTOK;
    size_t rb = (size_t)row * DMODEL;
    float4* qr = (float4*)(q + rb);
    float4* kr = (float4*)(k + rb);
    int ci = threadIdx.x;
    if (n == 0) {
        float4 t = qr[ci];
        t.x *= scale; t.y *= scale; t.z *= scale; t.w *= scale;
        qr[ci] = t;
        return;
    }
    int d = (ci * 4) & 63;
    const float4 cs = *(const float4*)(cosb + (size_t)(n - 1) * HD + d);
    const float4 sn = *(const float4*)(sinb + (size_t)(n - 1) * HD + d);
    float4 t = qr[ci], o;
    o.x = t.x * cs.x - t.y * sn.x;
    o.y = t.y * cs.y + t.x * sn.y;
    o.z = t.z * cs.z - t.w * sn.z;
    o.w = t.w * cs.w + t.z * sn.w;
    o.x *= scale; o.y *= scale; o.z *= scale; o.w *= scale;
    qr[ci] = o;
    t = kr[ci];
    o.x = t.x * cs.x - t.y * sn.x;
    o.y = t.y * cs.y + t.x * sn.y;
    o.z = t.z * cs.z - t.w * sn.z;
    o.w = t.w * cs.w + t.z * sn.w;
    kr[ci] = o;
}

// ---------------- fused attention: one block per (b,h) ----------------------
#define ATTN_SMEM_FLOATS (2 * 257 * 65 + 964 + 8 * 264 + 8 * 64)
__global__ void __launch_bounds__(256) attn_kernel(const float* __restrict__ q,
                                                   const float* __restrict__ k,
                                                   const float* __restrict__ v,
                                                   const float* __restrict__ table,
                                                   float* __restrict__ out)
{
    extern __shared__ float sm[];
    float* Ks = sm;
    float* Vs = Ks + 257 * 65;
    float* bs = Vs + 257 * 65;
    float* ps = bs + 964;
    float* qs = ps + 8 * 264;

    int bh = blockIdx.x;
    int b = bh >> 4, h = bh & 15;
    int tid = threadIdx.x, lane = tid & 31, w = tid >> 5;
    size_t base = (size_t)b * NTOK * DMODEL + (size_t)h * HD;

    for (int i = tid; i < NTOK * HD; i += 256) {
        int r = i >> 6, c = i & 63;
        Ks[r * 65 + c] = k[base + (size_t)r * DMODEL + c];
        Vs[r * 65 + c] = v[base + (size_t)r * DMODEL + c];
    }
    for (int i = tid; i < 964; i += 256) bs[i] = table[(size_t)i * NHEAD + h];
    __syncthreads();

    for (int qi = w; qi < NTOK; qi += 8) {
        qs[w * 64 + lane]      = q[base + (size_t)qi * DMODEL + lane];
        qs[w * 64 + lane + 32] = q[base + (size_t)qi * DMODEL + lane + 32];
        __syncwarp();
        int pq = qi - 1, chq = pq >> 4, cwq = pq & 15;
        float e[9];
        float mx = -1e30f;
#pragma unroll
        for (int j = 0; j < 9; j++) {
            int kk = j * 32 + lane;
            float sc = -1e30f;
            if (kk < NTOK) {
                const float* krow = &Ks[kk * 65];
                const float* qrow = &qs[w * 64];
                float dot = 0.f;
#pragma unroll
                for (int d2 = 0; d2 < 64; d2++) dot += qrow[d2] * krow[d2];
                int idx;
                if (qi == 0 && kk == 0)      idx = 963;
                else if (qi == 0)            idx = 961;
                else if (kk == 0)            idx = 962;
                else {
                    int pk = kk - 1;
                    idx = (chq - (pk >> 4) + 15) * 31 + (cwq - (pk & 15) + 15);
                }
                sc = dot + bs[idx];
            }
            e[j] = sc;
            mx = fmaxf(mx, sc);
        }
#pragma unroll
        for (int o = 16; o; o >>= 1) mx = fmaxf(mx, __shfl_xor_sync(0xffffffffu, mx, o));
        float sum = 0.f;
#pragma unroll
        for (int j = 0; j < 9; j++) {
            e[j] = (e[j] > -1e29f) ? __expf(e[j] - mx) : 0.f;
            sum += e[j];
        }
#pragma unroll
        for (int o = 16; o; o >>= 1) sum += __shfl_xor_sync(0xffffffffu, sum, o);
        float inv = 1.f / sum;
        __syncwarp();
#pragma unroll
        for (int j = 0; j < 9; j++) {
            int kk = j * 32 + lane;
            if (kk < NTOK) ps[w * 264 + kk] = e[j] * inv;
        }
        __syncwarp();
        float a0 = 0.f, a1 = 0.f;
        const float* pp = &ps[w * 264];
        for (int kk = 0; kk < NTOK; kk++) {
            float pk = pp[kk];
            a0 += pk * Vs[kk * 65 + lane];
            a1 += pk * Vs[kk * 65 + lane + 32];
        }
        out[base + (size_t)qi * DMODEL + lane]      = a0;
        out[base + (size_t)qi * DMODEL + lane + 32] = a1;
    }
}

// ---------------- launch -----------------------------------------------------
extern "C" void kernel_launch(void* const* d_in, const int* in_sizes, int n_in,
                              void* d_out, int out_size)
{
    const float* x        = (const float*)d_in[0];
    const float* rope_cos = (const float*)d_in[1];
    const float* rope_sin = (const float*)d_in[2];
    const float* q_w      = (const float*)d_in[3];
    const float* q_b      = (const float*)d_in[4];
    const float* k_w      = (const float*)d_in[5];
    const float* v_w      = (const float*)d_in[6];
    const float* v_b      = (const float*)d_in[7];
    const float* table    = (const float*)d_in[8];
    const float* in_g     = (const float*)d_in[9];
    const float* in_b     = (const float*)d_in[10];
    const float* proj_w   = (const float*)d_in[11];
    const float* proj_b   = (const float*)d_in[12];
    const float* n1g      = (const float*)d_in[13];
    const float* n1b      = (const float*)d_in[14];
    const float* n2g      = (const float*)d_in[15];
    const float* n2b      = (const float*)d_in[16];
    const float* w1       = (const float*)d_in[17];
    const float* w1b      = (const float*)d_in[18];
    const float* w2       = (const float*)d_in[19];
    const float* w2b      = (const float*)d_in[20];
    const float* fg       = (const float*)d_in[21];
    const float* fb       = (const float*)d_in[22];
    const float* w3       = (const float*)d_in[23];
    const float* w3b      = (const float*)d_in[24];
    float* out = (float*)d_out;

    float *q, *k, *v, *att, *x1, *h1, *h2;
    __half *a16, *h16, *qw16, *kw16, *vw16, *pw16, *w116, *w216, *w316;
    cudaGetSymbolAddress((void**)&q,    g_q);
    cudaGetSymbolAddress((void**)&k,    g_k);
    cudaGetSymbolAddress((void**)&v,    g_v);
    cudaGetSymbolAddress((void**)&att,  g_att);
    cudaGetSymbolAddress((void**)&x1,   g_x1);
    cudaGetSymbolAddress((void**)&h1,   g_h1);
    cudaGetSymbolAddress((void**)&h2,   g_h2);
    cudaGetSymbolAddress((void**)&a16,  g_a16);
    cudaGetSymbolAddress((void**)&h16,  g_h16);
    cudaGetSymbolAddress((void**)&qw16, g_qw16);
    cudaGetSymbolAddress((void**)&kw16, g_kw16);
    cudaGetSymbolAddress((void**)&vw16, g_vw16);
    cudaGetSymbolAddress((void**)&pw16, g_pw16);
    cudaGetSymbolAddress((void**)&w116, g_w116);
    cudaGetSymbolAddress((void**)&w216, g_w216);
    cudaGetSymbolAddress((void**)&w316, g_w316);

    int attn_smem = ATTN_SMEM_FLOATS * 4;
    cudaFuncSetAttribute(attn_kernel, cudaFuncAttributeMaxDynamicSharedMemorySize, attn_smem);
    cudaFuncSetAttribute(tgemm<false>, cudaFuncAttributeMaxDynamicSharedMemorySize, SMEM_G);
    cudaFuncSetAttribute(tgemm<true>,  cudaFuncAttributeMaxDynamicSharedMemorySize, SMEM_G);

    dim3 blk(256);
    dim3 gD(DMODEL / 128, (T_TOK + 127) / 128);   // (8, 129)
    dim3 gH(HDIM / 128,   (T_TOK + 127) / 128);   // (32, 129)

    // 0) weight fp16 conversions
    const int n4_1M = DMODEL * DMODEL / 4;        // 262144
    const int n4_4M = HDIM * DMODEL / 4;          // 1048576
    cvt16<<<(n4_1M + 255) / 256, blk>>>(q_w,    qw16, n4_1M);
    cvt16<<<(n4_1M + 255) / 256, blk>>>(k_w,    kw16, n4_1M);
    cvt16<<<(n4_1M + 255) / 256, blk>>>(v_w,    vw16, n4_1M);
    cvt16<<<(n4_1M + 255) / 256, blk>>>(proj_w, pw16, n4_1M);
    cvt16<<<(n4_4M + 255) / 256, blk>>>(w1,     w116, n4_4M);
    cvt16<<<(n4_4M + 255) / 256, blk>>>(w2,     w216, n4_4M);
    cvt16<<<(n4_4M + 255) / 256, blk>>>(w3,     w316, n4_4M);

    // 1) norm1 -> fp16 plane
    ln16<DMODEL><<<T_TOK, blk>>>(x, n1g, n1b, a16);
    // 2) QKV projections (tensor cores, fp16 single pass)
    tgemm<false><<<gD, blk, SMEM_G>>>(a16, qw16, q_b,     nullptr, q, T_TOK, DMODEL, DMODEL);
    tgemm<false><<<gD, blk, SMEM_G>>>(a16, kw16, nullptr, nullptr, k, T_TOK, DMODEL, DMODEL);
    tgemm<false><<<gD, blk, SMEM_G>>>(a16, vw16, v_b,     nullptr, v, T_TOK, DMODEL, DMODEL);
    // 3) RoPE + q scaling
    rope_kernel<<<T_TOK, blk>>>(q, k, rope_cos, rope_sin);
    // 4) attention
    attn_kernel<<<BATCH * NHEAD, blk, attn_smem>>>(q, k, v, table, att);
    // 5) inner LN -> fp16, proj (+ residual with original x) -> x1
    ln16<DMODEL><<<T_TOK, blk>>>(att, in_g, in_b, a16);
    tgemm<true><<<gD, blk, SMEM_G>>>(a16, pw16, proj_b, x, x1, T_TOK, DMODEL, DMODEL);
    // 6) norm2 -> fp16
    ln16<DMODEL><<<T_TOK, blk>>>(x1, n2g, n2b, a16);
    // 7) FFN up projections
    tgemm<false><<<gH, blk, SMEM_G>>>(a16, w116, w1b, nullptr, h1, T_TOK, HDIM, DMODEL);
    tgemm<false><<<gH, blk, SMEM_G>>>(a16, w216, w2b, nullptr, h2, T_TOK, HDIM, DMODEL);
    // 8) silu(h1)*h2 -> ffn LN -> fp16
    silu_ln16<<<T_TOK, blk>>>(h1, h2, fg, fb, h16);
    // 9) down projection + residual -> out
    tgemm<true><<<gD, blk, SMEM_G>>>(h16, w316, w3b, x1, out, T_TOK, DMODEL, HDIM);
}

// round 8
// speedup vs baseline: 4.5394x; 1.0549x over previous
#include <cuda_runtime.h>
#include <cuda_fp16.h>
#include <stdint.h>
#include <math.h>

#define NTOK   257
#define BATCH  64
#define T_TOK  (BATCH * NTOK)   // 16448
#define DMODEL 1024
#define NHEAD  16
#define HD     64
#define HDIM   4096
#define LN_EPS 1e-5f
#define STRQ   3072              // fused qkv row stride

// ---------------- scratch (device globals; no allocations allowed) ----------
__device__ __align__(16) float g_qkv[(size_t)T_TOK * STRQ];
__device__ __align__(16) float g_att[(size_t)T_TOK * DMODEL];
__device__ __align__(16) float g_x1 [(size_t)T_TOK * DMODEL];
__device__ __align__(16) float g_h12[(size_t)T_TOK * 2 * HDIM];

__device__ __align__(16) __half g_a16[(size_t)T_TOK * DMODEL];
__device__ __align__(16) __half g_h16[(size_t)T_TOK * HDIM];
__device__ __align__(16) __half g_qkvw16[(size_t)3 * DMODEL * DMODEL];
__device__ __align__(16) __half g_pw16[(size_t)DMODEL * DMODEL];
__device__ __align__(16) __half g_w1216[(size_t)2 * HDIM * DMODEL];
__device__ __align__(16) __half g_w316[(size_t)DMODEL * HDIM];
__device__ __align__(16) float  g_qkvb[3 * DMODEL];
__device__ __align__(16) float  g_w12b[2 * HDIM];

// ---------------- fp32 -> fp16 helpers --------------------------------------
__device__ __forceinline__ uint2 pack16(float4 t)
{
    __half2 a = __floats2half2_rn(t.x, t.y);
    __half2 b = __floats2half2_rn(t.z, t.w);
    uint2 r;
    r.x = *(uint32_t*)&a;
    r.y = *(uint32_t*)&b;
    return r;
}

__global__ void __launch_bounds__(256) cvt16(const float* __restrict__ x,
                                             __half* __restrict__ o,
                                             int n4)
{
    int i = blockIdx.x * 256 + threadIdx.x;
    if (i >= n4) return;
    ((uint2*)o)[i] = pack16(((const float4*)x)[i]);
}

__global__ void __launch_bounds__(256) pack_qkv_bias(const float* __restrict__ qb,
                                                     const float* __restrict__ vb,
                                                     float* __restrict__ o)
{
    int i = blockIdx.x * 256 + threadIdx.x;
    if (i >= 3 * DMODEL) return;
    o[i] = (i < DMODEL) ? qb[i] : ((i < 2 * DMODEL) ? 0.f : vb[i - 2 * DMODEL]);
}

__global__ void __launch_bounds__(256) pack_w12_bias(const float* __restrict__ b1,
                                                     const float* __restrict__ b2,
                                                     float* __restrict__ o)
{
    int i = blockIdx.x * 256 + threadIdx.x;
    if (i >= 2 * HDIM) return;
    o[i] = (i < HDIM) ? b1[i] : b2[i - HDIM];
}

// ---------------- mma.sync GEMM: C = A*B^T (+bias)(+res), fp32 out ----------
// CTA tile 128x256, 8 warps (2x4), warp tile 64x64, K chunk 32, double buffer.
#define RSB    80                 // smem row stride bytes (40 halves)
#define APLANE (128 * RSB)        // 10240
#define BPLANE (256 * RSB)        // 20480
#define STAGE  (APLANE + BPLANE)  // 30720
#define SMEM_G (2 * STAGE)        // 61440

#define LDSM4(r0, r1, r2, r3, addr) \
    asm volatile("ldmatrix.sync.aligned.m8n8.x4.shared.b16 {%0,%1,%2,%3}, [%4];" \
                 : "=r"(r0), "=r"(r1), "=r"(r2), "=r"(r3) : "r"(addr))

#define MMA16816(c, a, b) \
    asm volatile("mma.sync.aligned.m16n8k16.row.col.f32.f16.f16.f32 " \
                 "{%0,%1,%2,%3}, {%4,%5,%6,%7}, {%8,%9}, {%0,%1,%2,%3};" \
                 : "+f"((c)[0]), "+f"((c)[1]), "+f"((c)[2]), "+f"((c)[3]) \
                 : "r"((a)[0]), "r"((a)[1]), "r"((a)[2]), "r"((a)[3]), \
                   "r"((b)[0]), "r"((b)[1]))

template<bool RES>
__global__ void __launch_bounds__(256) tgemm(const __half* __restrict__ A,
                                             const __half* __restrict__ B,
                                             const float* __restrict__ bias,
                                             const float* __restrict__ res,
                                             float* __restrict__ C,
                                             int M, int N, int K)
{
    extern __shared__ __align__(16) char dsm[];
    uint32_t sb = (uint32_t)__cvta_generic_to_shared(dsm);

    int tid = threadIdx.x, lane = tid & 31, warp = tid >> 5;
    int wm = warp >> 2, wn = warp & 3;           // warp grid 2 x 4
    int m0 = blockIdx.y * 128, n0 = blockIdx.x * 256;

    float acc[4][8][4];
#pragma unroll
    for (int i = 0; i < 4; i++)
#pragma unroll
        for (int j = 0; j < 8; j++)
#pragma unroll
            for (int r = 0; r < 4; r++) acc[i][j][r] = 0.f;

    auto issue_loads = [&](int c) {
        int k0 = c * 32;
        uint32_t sbuf = sb + (uint32_t)(c & 1) * STAGE;
#pragma unroll
        for (int i = 0; i < 6; i++) {
            int gi = i * 256 + tid;       // 0..1535
            if (gi < 512) {               // A plane: 128 rows x 4 chunks
                int row = gi >> 2, cc = gi & 3;
                int grow = m0 + row;
                int sz = 16;
                if (grow >= M) { grow = 0; sz = 0; }
                const void* src = A + (size_t)grow * K + k0 + cc * 8;
                uint32_t dst = sbuf + (uint32_t)(row * RSB + cc * 16);
                asm volatile("cp.async.ca.shared.global [%0], [%1], 16, %2;"
                             :: "r"(dst), "l"(src), "r"(sz));
            } else {                      // B plane: 256 rows x 4 chunks
                int idx = gi - 512;
                int row = idx >> 2, cc = idx & 3;
                const void* src = B + (size_t)(n0 + row) * K + k0 + cc * 8;
                uint32_t dst = sbuf + APLANE + (uint32_t)(row * RSB + cc * 16);
                asm volatile("cp.async.ca.shared.global [%0], [%1], 16, 16;"
                             :: "r"(dst), "l"(src));
            }
        }
        asm volatile("cp.async.commit_group;" ::: "memory");
    };

    int KT = K >> 5;
    issue_loads(0);

    for (int c = 0; c < KT; c++) {
        if (c + 1 < KT) {
            issue_loads(c + 1);
            asm volatile("cp.async.wait_group 1;" ::: "memory");
        } else {
            asm volatile("cp.async.wait_group 0;" ::: "memory");
        }
        __syncthreads();

        uint32_t sbuf = sb + (uint32_t)(c & 1) * STAGE;
#pragma unroll
        for (int kk = 0; kk < 32; kk += 16) {
            uint32_t af[4][4], bf[8][2];
#pragma unroll
            for (int mi = 0; mi < 4; mi++) {
                int arow = wm * 64 + mi * 16 + (lane & 15);
                uint32_t aoff = (uint32_t)(arow * RSB + (kk + (lane >> 4) * 8) * 2);
                LDSM4(af[mi][0], af[mi][1], af[mi][2], af[mi][3], sbuf + aoff);
            }
#pragma unroll
            for (int nj = 0; nj < 4; nj++) {
                int g = lane >> 3;
                int nrow = wn * 64 + nj * 16 + (g >> 1) * 8 + (lane & 7);
                uint32_t boff = (uint32_t)(nrow * RSB + (kk + (g & 1) * 8) * 2);
                LDSM4(bf[nj*2][0], bf[nj*2][1], bf[nj*2+1][0], bf[nj*2+1][1],
                      sbuf + APLANE + boff);
            }
#pragma unroll
            for (int mi = 0; mi < 4; mi++)
#pragma unroll
                for (int ni = 0; ni < 8; ni++)
                    MMA16816(acc[mi][ni], af[mi], bf[ni]);
        }
        __syncthreads();
    }

    // epilogue
#pragma unroll
    for (int mi = 0; mi < 4; mi++) {
#pragma unroll
        for (int ni = 0; ni < 8; ni++) {
            int r0 = m0 + wm * 64 + mi * 16 + (lane >> 2);
            int col = n0 + wn * 64 + ni * 8 + (lane & 3) * 2;
            float bx = 0.f, by = 0.f;
            if (bias) { bx = bias[col]; by = bias[col + 1]; }
            float2 v0, v1;
            v0.x = acc[mi][ni][0] + bx; v0.y = acc[mi][ni][1] + by;
            v1.x = acc[mi][ni][2] + bx; v1.y = acc[mi][ni][3] + by;
            if (r0 < M) {
                size_t off = (size_t)r0 * N + col;
                if (RES) { float2 rr = *(const float2*)&res[off]; v0.x += rr.x; v0.y += rr.y; }
                *(float2*)&C[off] = v0;
            }
            if (r0 + 8 < M) {
                size_t off = (size_t)(r0 + 8) * N + col;
                if (RES) { float2 rr = *(const float2*)&res[off]; v1.x += rr.x; v1.y += rr.y; }
                *(float2*)&C[off] = v1;
            }
        }
    }
}

// ---------------- LayerNorm -> fp16 plane ------------------------------------
template<int W>
__global__ void __launch_bounds__(256) ln16(const float* __restrict__ x,
                                            const float* __restrict__ g,
                                            const float* __restrict__ b,
                                            __half* __restrict__ o16)
{
    constexpr int V = W / 1024;
    __shared__ float red0[8], red1[8];
    __shared__ float stats[2];
    size_t rb = (size_t)blockIdx.x * W;
    const float4* xr = (const float4*)(x + rb);
    float4 vv[V];
    float s = 0.f, s2 = 0.f;
#pragma unroll
    for (int i = 0; i < V; i++) {
        float4 t = xr[threadIdx.x + i * 256];
        vv[i] = t;
        s  += t.x + t.y + t.z + t.w;
        s2 += t.x*t.x + t.y*t.y + t.z*t.z + t.w*t.w;
    }
#pragma unroll
    for (int o = 16; o; o >>= 1) {
        s  += __shfl_xor_sync(0xffffffffu, s,  o);
        s2 += __shfl_xor_sync(0xffffffffu, s2, o);
    }
    if ((threadIdx.x & 31) == 0) { red0[threadIdx.x >> 5] = s; red1[threadIdx.x >> 5] = s2; }
    __syncthreads();
    if (threadIdx.x == 0) {
        float a = 0.f, c = 0.f;
#pragma unroll
        for (int i = 0; i < 8; i++) { a += red0[i]; c += red1[i]; }
        float mu  = a / (float)W;
        float var = c / (float)W - mu * mu;
        stats[0] = mu;
        stats[1] = rsqrtf(var + LN_EPS);
    }
    __syncthreads();
    float mu = stats[0], inv = stats[1];
    const float4* g4 = (const float4*)g;
    const float4* b4 = (const float4*)b;
#pragma unroll
    for (int i = 0; i < V; i++) {
        int c = threadIdx.x + i * 256;
        float4 gg = g4[c], bb = b4[c], t = vv[i], o;
        o.x = (t.x - mu) * inv * gg.x + bb.x;
        o.y = (t.y - mu) * inv * gg.y + bb.y;
        o.z = (t.z - mu) * inv * gg.z + bb.z;
        o.w = (t.w - mu) * inv * gg.w + bb.w;
        ((uint2*)(o16 + rb))[c] = pack16(o);
    }
}

// ---------------- fused SiLU(x1)*x2 -> LayerNorm -> fp16 (from fused h12) ---
__global__ void __launch_bounds__(256) silu_ln16(const float* __restrict__ h12,
                                                 const float* __restrict__ g,
                                                 const float* __restrict__ b,
                                                 __half* __restrict__ o16)
{
    constexpr int W = HDIM;
    constexpr int V = W / 1024;
    __shared__ float red0[8], red1[8];
    __shared__ float stats[2];
    size_t rb12 = (size_t)blockIdx.x * (2 * HDIM);
    size_t rb   = (size_t)blockIdx.x * W;
    const float4* ar = (const float4*)(h12 + rb12);
    const float4* cr = (const float4*)(h12 + rb12 + HDIM);
    float4 vv[V];
    float s = 0.f, s2 = 0.f;
#pragma unroll
    for (int i = 0; i < V; i++) {
        float4 a = ar[threadIdx.x + i * 256];
        float4 c = cr[threadIdx.x + i * 256];
        float4 t;
        t.x = a.x / (1.f + __expf(-a.x)) * c.x;
        t.y = a.y / (1.f + __expf(-a.y)) * c.y;
        t.z = a.z / (1.f + __expf(-a.z)) * c.z;
        t.w = a.w / (1.f + __expf(-a.w)) * c.w;
        vv[i] = t;
        s  += t.x + t.y + t.z + t.w;
        s2 += t.x*t.x + t.y*t.y + t.z*t.z + t.w*t.w;
    }
#pragma unroll
    for (int o = 16; o; o >>= 1) {
        s  += __shfl_xor_sync(0xffffffffu, s,  o);
        s2 += __shfl_xor_sync(0xffffffffu, s2, o);
    }
    if ((threadIdx.x & 31) == 0) { red0[threadIdx.x >> 5] = s; red1[threadIdx.x >> 5] = s2; }
    __syncthreads();
    if (threadIdx.x == 0) {
        float a = 0.f, c = 0.f;
#pragma unroll
        for (int i = 0; i < 8; i++) { a += red0[i]; c += red1[i]; }
        float mu  = a / (float)W;
        float var = c / (float)W - mu * mu;
        stats[0] = mu;
        stats[1] = rsqrtf(var + LN_EPS);
    }
    __syncthreads();
    float mu = stats[0], inv = stats[1];
    const float4* g4 = (const float4*)g;
    const float4* b4 = (const float4*)b;
#pragma unroll
    for (int i = 0; i < V; i++) {
        int c = threadIdx.x + i * 256;
        float4 gg = g4[c], bb = b4[c], t = vv[i], o;
        o.x = (t.x - mu) * inv * gg.x + bb.x;
        o.y = (t.y - mu) * inv * gg.y + bb.y;
        o.z = (t.z - mu) * inv * gg.z + bb.z;
        o.w = (t.w - mu) * inv * gg.w + bb.w;
        ((uint2*)(o16 + rb))[c] = pack16(o);
    }
}

// ---------------- RoPE on q,k in fused qkv buffer; scale q ------------------
__global__ void __launch_bounds__(256) rope_kernel(float* __restrict__ qkv,
                                                   const float* __restrict__ cosb,
                                                   const float* __restrict__ sinb)
{
    const float scale = 0.125f;
    int row = blockIdx.x;
    int n = row % NTOK;
    float4* qr = (float4*)(qkv + (size_t)row * STRQ);
    float4* kr = (float4*)(qkv + (size_t)row * STRQ + DMODEL);
    int ci = threadIdx.x;
    if (n == 0) {
        float4 t = qr[ci];
        t.x *= scale; t.y *= scale; t.z *= scale; t.w *= scale;
        qr[ci] = t;
        return;
    }
    int d = (ci * 4) & 63;
    const float4 cs = *(const float4*)(cosb + (size_t)(n - 1) * HD + d);
    const float4 sn = *(const float4*)(sinb + (size_t)(n - 1) * HD + d);
    float4 t = qr[ci], o;
    o.x = t.x * cs.x - t.y * sn.x;
    o.y = t.y * cs.y + t.x * sn.y;
    o.z = t.z * cs.z - t.w * sn.z;
    o.w = t.w * cs.w + t.z * sn.w;
    o.x *= scale; o.y *= scale; o.z *= scale; o.w *= scale;
    qr[ci] = o;
    t = kr[ci];
    o.x = t.x * cs.x - t.y * sn.x;
    o.y = t.y * cs.y + t.x * sn.y;
    o.z = t.z * cs.z - t.w * sn.z;
    o.w = t.w * cs.w + t.z * sn.w;
    kr[ci] = o;
}

// ---------------- attention v2: one block per (b,h), 8 q-rows per warp ------
// smem: KsT[64][289] | Vs[257][65] | bias[964] | qs[8w][8][64] | psH[8w][8][264]
#define KST_STR 289
#define ATTN_SMEM_BYTES ((64 * KST_STR + 257 * 65 + 964 + 8 * 8 * 64) * 4 + 8 * 8 * 264 * 2)

__global__ void __launch_bounds__(256) attn_kernel(const float* __restrict__ qkv,
                                                   const float* __restrict__ table,
                                                   float* __restrict__ out)
{
    extern __shared__ float sm[];
    float* KsT = sm;
    float* Vs  = KsT + 64 * KST_STR;
    float* bs  = Vs + 257 * 65;
    float* qs  = bs + 964;
    __half* psH = (__half*)(qs + 8 * 8 * 64);

    int bh = blockIdx.x;
    int b = bh >> 4, h = bh & 15;
    int tid = threadIdx.x, lane = tid & 31, w = tid >> 5;
    const float* qg = qkv + (size_t)b * NTOK * STRQ + h * HD;
    const float* kg = qg + DMODEL;
    const float* vg = qg + 2 * DMODEL;

    for (int i = tid; i < NTOK * HD; i += 256) {
        int r = i >> 6, c = i & 63;
        KsT[c * KST_STR + r] = kg[(size_t)r * STRQ + c];
        Vs [r * 65 + c]      = vg[(size_t)r * STRQ + c];
    }
    // zero K tail columns 257..288
    for (int i = tid; i < 64 * 32; i += 256) {
        int d = i >> 5;
        KsT[d * KST_STR + 257 + (i & 31)] = 0.f;
    }
    for (int i = tid; i < 964; i += 256) bs[i] = table[(size_t)i * NHEAD + h];
    __syncthreads();

    float* qsw = qs + w * 8 * 64;
    __half* psw = psH + w * 8 * 264;

    for (int qb = w * 8; qb < NTOK; qb += 64) {
        // load 8 q rows (zeros for invalid)
#pragma unroll
        for (int qi8 = 0; qi8 < 8; qi8++) {
            int qi = qb + qi8;
            float v0 = 0.f, v1 = 0.f;
            if (qi < NTOK) {
                v0 = qg[(size_t)qi * STRQ + lane];
                v1 = qg[(size_t)qi * STRQ + lane + 32];
            }
            qsw[qi8 * 64 + lane]      = v0;
            qsw[qi8 * 64 + lane + 32] = v1;
        }
        __syncwarp();

        // QK^T: e[qi8][j], kk = j*32+lane
        float e[8][9];
#pragma unroll
        for (int a = 0; a < 8; a++)
#pragma unroll
            for (int j = 0; j < 9; j++) e[a][j] = 0.f;

        for (int d = 0; d < 64; d++) {
            float kj[9];
#pragma unroll
            for (int j = 0; j < 9; j++) kj[j] = KsT[d * KST_STR + j * 32 + lane];
#pragma unroll
            for (int a = 0; a < 8; a++) {
                float qv = qsw[a * 64 + d];
#pragma unroll
                for (int j = 0; j < 9; j++) e[a][j] += qv * kj[j];
            }
        }

        // softmax per q-row, write P (fp16)
#pragma unroll
        for (int a = 0; a < 8; a++) {
            int qi = qb + a;
            int pq = qi - 1, chq = pq >> 4, cwq = pq & 15;
            float ee[9];
            float mx = -1e30f;
#pragma unroll
            for (int j = 0; j < 9; j++) {
                int kk = j * 32 + lane;
                float sc = -1e30f;
                if (kk < NTOK && qi < NTOK) {
                    int idx;
                    if (qi == 0 && kk == 0)      idx = 963;
                    else if (qi == 0)            idx = 961;
                    else if (kk == 0)            idx = 962;
                    else {
                        int pk = kk - 1;
                        idx = (chq - (pk >> 4) + 15) * 31 + (cwq - (pk & 15) + 15);
                    }
                    sc = e[a][j] + bs[idx];
                }
                ee[j] = sc;
                mx = fmaxf(mx, sc);
            }
#pragma unroll
            for (int o = 16; o; o >>= 1) mx = fmaxf(mx, __shfl_xor_sync(0xffffffffu, mx, o));
            float sum = 0.f;
#pragma unroll
            for (int j = 0; j < 9; j++) {
                ee[j] = (ee[j] > -1e29f) ? __expf(ee[j] - mx) : 0.f;
                sum += ee[j];
            }
#pragma unroll
            for (int o = 16; o; o >>= 1) sum += __shfl_xor_sync(0xffffffffu, sum, o);
            float inv = 1.f / sum;
#pragma unroll
            for (int j = 0; j < 9; j++) {
                int kk = j * 32 + lane;
                if (kk < NTOK) psw[a * 264 + kk] = __float2half(ee[j] * inv);
            }
        }
        __syncwarp();

        // AV: a[qi8][2], pairs of kk
        float av[8][2];
#pragma unroll
        for (int a = 0; a < 8; a++) { av[a][0] = 0.f; av[a][1] = 0.f; }

        for (int kp = 0; kp < 128; kp++) {
            int kk = kp * 2;
            float v0a = Vs[kk * 65 + lane];
            float v1a = Vs[kk * 65 + lane + 32];
            float v0b = Vs[(kk + 1) * 65 + lane];
            float v1b = Vs[(kk + 1) * 65 + lane + 32];
#pragma unroll
            for (int a = 0; a < 8; a++) {
                __half2 p2 = *(const __half2*)&psw[a * 264 + kk];
                float2 pf = __half22float2(p2);
                av[a][0] += pf.x * v0a + pf.y * v0b;
                av[a][1] += pf.x * v1a + pf.y * v1b;
            }
        }
        {
            float v0 = Vs[256 * 65 + lane];
            float v1 = Vs[256 * 65 + lane + 32];
#pragma unroll
            for (int a = 0; a < 8; a++) {
                float p = __half2float(psw[a * 264 + 256]);
                av[a][0] += p * v0;
                av[a][1] += p * v1;
            }
        }
#pragma unroll
        for (int a = 0; a < 8; a++) {
            int qi = qb + a;
            if (qi < NTOK) {
                size_t off = ((size_t)b * NTOK + qi) * DMODEL + h * HD;
                out[off + lane]      = av[a][0];
                out[off + lane + 32] = av[a][1];
            }
        }
        __syncwarp();
    }
}

// ---------------- launch -----------------------------------------------------
extern "C" void kernel_launch(void* const* d_in, const int* in_sizes, int n_in,
                              void* d_out, int out_size)
{
    const float* x        = (const float*)d_in[0];
    const float* rope_cos = (const float*)d_in[1];
    const float* rope_sin = (const float*)d_in[2];
    const float* q_w      = (const float*)d_in[3];
    const float* q_b      = (const float*)d_in[4];
    const float* k_w      = (const float*)d_in[5];
    const float* v_w      = (const float*)d_in[6];
    const float* v_b      = (const float*)d_in[7];
    const float* table    = (const float*)d_in[8];
    const float* in_g     = (const float*)d_in[9];
    const float* in_b     = (const float*)d_in[10];
    const float* proj_w   = (const float*)d_in[11];
    const float* proj_b   = (const float*)d_in[12];
    const float* n1g      = (const float*)d_in[13];
    const float* n1b      = (const float*)d_in[14];
    const float* n2g      = (const float*)d_in[15];
    const float* n2b      = (const float*)d_in[16];
    const float* w1       = (const float*)d_in[17];
    const float* w1b      = (const float*)d_in[18];
    const float* w2       = (const float*)d_in[19];
    const float* w2b      = (const float*)d_in[20];
    const float* fg       = (const float*)d_in[21];
    const float* fb       = (const float*)d_in[22];
    const float* w3       = (const float*)d_in[23];
    const float* w3b      = (const float*)d_in[24];
    float* out = (float*)d_out;

    float *qkv, *att, *x1, *h12, *qkvb, *w12b;
    __half *a16, *h16, *qkvw16, *pw16, *w1216, *w316;
    cudaGetSymbolAddress((void**)&qkv,    g_qkv);
    cudaGetSymbolAddress((void**)&att,    g_att);
    cudaGetSymbolAddress((void**)&x1,     g_x1);
    cudaGetSymbolAddress((void**)&h12,    g_h12);
    cudaGetSymbolAddress((void**)&a16,    g_a16);
    cudaGetSymbolAddress((void**)&h16,    g_h16);
    cudaGetSymbolAddress((void**)&qkvw16, g_qkvw16);
    cudaGetSymbolAddress((void**)&pw16,   g_pw16);
    cudaGetSymbolAddress((void**)&w1216,  g_w1216);
    cudaGetSymbolAddress((void**)&w316,   g_w316);
    cudaGetSymbolAddress((void**)&qkvb,   g_qkvb);
    cudaGetSymbolAddress((void**)&w12b,   g_w12b);

    cudaFuncSetAttribute(attn_kernel, cudaFuncAttributeMaxDynamicSharedMemorySize, ATTN_SMEM_BYTES);
    cudaFuncSetAttribute(tgemm<false>, cudaFuncAttributeMaxDynamicSharedMemorySize, SMEM_G);
    cudaFuncSetAttribute(tgemm<true>,  cudaFuncAttributeMaxDynamicSharedMemorySize, SMEM_G);

    dim3 blk(256);
    dim3 gQKV(3 * DMODEL / 256, (T_TOK + 127) / 128);   // (12, 129)
    dim3 gP(DMODEL / 256,       (T_TOK + 127) / 128);   // (4, 129)
    dim3 gW12(2 * HDIM / 256,   (T_TOK + 127) / 128);   // (32, 129)

    // 0) weight fp16 conversions (into fused buffers) + bias packing
    const int n4_1M = DMODEL * DMODEL / 4;
    const int n4_4M = HDIM * DMODEL / 4;
    cvt16<<<(n4_1M + 255) / 256, blk>>>(q_w,    qkvw16,                          n4_1M);
    cvt16<<<(n4_1M + 255) / 256, blk>>>(k_w,    qkvw16 + (size_t)DMODEL * DMODEL,     n4_1M);
    cvt16<<<(n4_1M + 255) / 256, blk>>>(v_w,    qkvw16 + (size_t)2 * DMODEL * DMODEL, n4_1M);
    cvt16<<<(n4_1M + 255) / 256, blk>>>(proj_w, pw16,                            n4_1M);
    cvt16<<<(n4_4M + 255) / 256, blk>>>(w1,     w1216,                           n4_4M);
    cvt16<<<(n4_4M + 255) / 256, blk>>>(w2,     w1216 + (size_t)HDIM * DMODEL,   n4_4M);
    cvt16<<<(n4_4M + 255) / 256, blk>>>(w3,     w316,                            n4_4M);
    pack_qkv_bias<<<(3 * DMODEL + 255) / 256, blk>>>(q_b, v_b, qkvb);
    pack_w12_bias<<<(2 * HDIM + 255) / 256, blk>>>(w1b, w2b, w12b);

    // 1) norm1 -> fp16
    ln16<DMODEL><<<T_TOK, blk>>>(x, n1g, n1b, a16);
    // 2) fused QKV projection
    tgemm<false><<<gQKV, blk, SMEM_G>>>(a16, qkvw16, qkvb, nullptr, qkv, T_TOK, 3 * DMODEL, DMODEL);
    // 3) RoPE + q scaling
    rope_kernel<<<T_TOK, blk>>>(qkv, rope_cos, rope_sin);
    // 4) attention
    attn_kernel<<<BATCH * NHEAD, blk, ATTN_SMEM_BYTES>>>(qkv, table, att);
    // 5) inner LN -> fp16, proj (+ residual with x) -> x1
    ln16<DMODEL><<<T_TOK, blk>>>(att, in_g, in_b, a16);
    tgemm<true><<<gP, blk, SMEM_G>>>(a16, pw16, proj_b, x, x1, T_TOK, DMODEL, DMODEL);
    // 6) norm2 -> fp16
    ln16<DMODEL><<<T_TOK, blk>>>(x1, n2g, n2b, a16);
    // 7) fused FFN up projection (w1|w2)
    tgemm<false><<<gW12, blk, SMEM_G>>>(a16, w1216, w12b, nullptr, h12, T_TOK, 2 * HDIM, DMODEL);
    // 8) silu(x1h)*x2h -> ffn LN -> fp16
    silu_ln16<<<T_TOK, blk>>>(h12, fg, fb, h16);
    // 9) down projection + residual -> out
    tgemm<true><<<gP, blk, SMEM_G>>>(h16, w316, w3b, x1, out, T_TOK, DMODEL, HDIM);
}